// round 2
// baseline (speedup 1.0000x reference)
#include <cuda_runtime.h>
#include <math.h>

// Problem constants
#define NG   8       // blocks
#define NH   512     // hidden per block
#define NI   1028    // GRU input size (A + L*C)
#define NB   128     // batch
#define NT   64      // seq len
#define N3H  1536    // 3*NH
#define NTOT (NG*N3H)   // 12288
#define MTOT (NB*NT)    // 8192

// Scratch (allocation-free rule: __device__ globals)
__device__ float g_xproj[(size_t)MTOT * NTOT];   // (B*T, G*3H) input projections, ~402MB
__device__ float g_h[2][NB * NG * NH];           // hidden state ping-pong

// ---------------------------------------------------------------------------
// Copy initial hidden state into ping-pong buffer 0
// ---------------------------------------------------------------------------
__global__ void init_h(const float* __restrict__ h0) {
    int i = blockIdx.x * blockDim.x + threadIdx.x;
    if (i < NB * NG * NH) g_h[0][i] = h0[i];
}

// ---------------------------------------------------------------------------
// x_proj GEMM: C[m, n] = sum_k X[m,k] * Wih[n,k] + bih[n]
//   m = b*T + t (8192), n = g*1536 + j (12288), k over I=1028
//   X[m,k] = k<4 ? a[m,k] : z[m, k-4]   (concat(a, z))
// 128x128 tile, 256 threads, 8x8 per-thread microtile, K-chunks of 8.
// ---------------------------------------------------------------------------
__global__ __launch_bounds__(256) void xproj_gemm(
    const float* __restrict__ z, const float* __restrict__ a,
    const float* __restrict__ Wih, const float* __restrict__ bih)
{
    __shared__ float As[8][128];
    __shared__ float Bs[8][128];

    const int tid = threadIdx.x;
    const int tx = tid & 15, ty = tid >> 4;
    const int m0 = blockIdx.y * 128, n0 = blockIdx.x * 128;

    float c[8][8] = {};

    const int mm  = tid >> 1;          // 0..127 row for loading
    const int kkb = (tid & 1) * 4;     // 0 or 4

    for (int kc = 0; kc < 129; ++kc) { // ceil(1028/8)
        const int k0 = kc * 8;
        #pragma unroll
        for (int r = 0; r < 4; ++r) {
            const int k = k0 + kkb + r;
            float v = 0.f;
            if (k < 4)        v = a[(m0 + mm) * 4 + k];
            else if (k < NI)  v = z[(size_t)(m0 + mm) * 1024 + (k - 4)];
            As[kkb + r][mm] = v;
            float w = 0.f;
            if (k < NI) w = Wih[(size_t)(n0 + mm) * NI + k];
            Bs[kkb + r][mm] = w;
        }
        __syncthreads();
        #pragma unroll
        for (int kk = 0; kk < 8; ++kk) {
            float4 a0 = *(const float4*)&As[kk][ty * 8];
            float4 a1 = *(const float4*)&As[kk][ty * 8 + 4];
            float4 b0 = *(const float4*)&Bs[kk][tx * 8];
            float4 b1 = *(const float4*)&Bs[kk][tx * 8 + 4];
            float av[8] = {a0.x,a0.y,a0.z,a0.w,a1.x,a1.y,a1.z,a1.w};
            float bv[8] = {b0.x,b0.y,b0.z,b0.w,b1.x,b1.y,b1.z,b1.w};
            #pragma unroll
            for (int i = 0; i < 8; ++i)
                #pragma unroll
                for (int j = 0; j < 8; ++j)
                    c[i][j] = fmaf(av[i], bv[j], c[i][j]);
        }
        __syncthreads();
    }

    #pragma unroll
    for (int i = 0; i < 8; ++i) {
        const size_t row = (size_t)(m0 + ty * 8 + i) * NTOT + n0 + tx * 8;
        #pragma unroll
        for (int j = 0; j < 8; ++j)
            g_xproj[row + j] = c[i][j] + bih[n0 + tx * 8 + j];
    }
}

// ---------------------------------------------------------------------------
// One GRU timestep, fused: hp = h @ Whh^T (+bhh), gates, h update, output.
// Grid: 128 CTAs = g(8) x chunk(16); each CTA computes, for all 128 batch
// rows, the 32 H-columns [c0, c0+32) of block g -- and for each such column
// ALL THREE gate rows {c, H+c, 2H+c}, gate-aligned inside one thread's
// accumulators so the nonlinearity needs no cross-thread exchange.
// ---------------------------------------------------------------------------
__global__ __launch_bounds__(256) void gru_step(
    const float* __restrict__ Whh, const float* __restrict__ bhh,
    float* __restrict__ out, int t)
{
    __shared__ float As[8][128];   // h tile: [k][batch]
    __shared__ float Bs[8][96];    // W tile: [k][3 gates x 32 cols]

    const float* __restrict__ hin  = g_h[t & 1];
    float* __restrict__       hout = g_h[(t + 1) & 1];

    const int tid = threadIdx.x;
    const int tx = tid & 15, ty = tid >> 4;
    const int g  = blockIdx.x >> 4;
    const int c0 = (blockIdx.x & 15) * 32;

    float acc[8][6] = {};          // 8 batch rows x {r,z,n}x2 columns

    const int mm  = tid >> 1;
    const int kkb = (tid & 1) * 4;
    const int ca = tx * 2, cb = tx * 2 + 1;

    for (int kc = 0; kc < 64; ++kc) {   // K = 512
        const int k0 = kc * 8;
        #pragma unroll
        for (int r = 0; r < 4; ++r)
            As[kkb + r][mm] = hin[mm * (NG * NH) + g * NH + k0 + kkb + r];
        #pragma unroll
        for (int r = 0; r < 3; ++r) {
            const int idx = r * 256 + tid;       // 0..767
            const int kk = idx & 7, cc = idx >> 3;
            const int wrow = g * N3H + (cc >> 5) * NH + c0 + (cc & 31);
            Bs[kk][cc] = Whh[(size_t)wrow * NH + k0 + kk];
        }
        __syncthreads();
        #pragma unroll
        for (int kk = 0; kk < 8; ++kk) {
            float4 a0 = *(const float4*)&As[kk][ty * 8];
            float4 a1 = *(const float4*)&As[kk][ty * 8 + 4];
            float av[8] = {a0.x,a0.y,a0.z,a0.w,a1.x,a1.y,a1.z,a1.w};
            float bv[6];
            bv[0] = Bs[kk][ca];      bv[1] = Bs[kk][ca + 32]; bv[2] = Bs[kk][ca + 64];
            bv[3] = Bs[kk][cb];      bv[4] = Bs[kk][cb + 32]; bv[5] = Bs[kk][cb + 64];
            #pragma unroll
            for (int i = 0; i < 8; ++i)
                #pragma unroll
                for (int j = 0; j < 6; ++j)
                    acc[i][j] = fmaf(av[i], bv[j], acc[i][j]);
        }
        __syncthreads();
    }

    // Fused gate epilogue
    #pragma unroll
    for (int i = 0; i < 8; ++i) {
        const int b = ty * 8 + i;
        #pragma unroll
        for (int p = 0; p < 2; ++p) {
            const int c = c0 + tx * 2 + p;
            const float hr = acc[i][p * 3 + 0] + bhh[g * N3H + c];
            const float hz = acc[i][p * 3 + 1] + bhh[g * N3H + NH + c];
            const float hn = acc[i][p * 3 + 2] + bhh[g * N3H + 2 * NH + c];
            const size_t xb = (size_t)(b * NT + t) * NTOT + g * N3H;
            const float xr = g_xproj[xb + c];
            const float xz = g_xproj[xb + NH + c];
            const float xn = g_xproj[xb + 2 * NH + c];
            const float rr = 1.f / (1.f + __expf(-(xr + hr)));
            const float uu = 1.f / (1.f + __expf(-(xz + hz)));
            const float nn = tanhf(xn + rr * hn);
            const float hold = hin[b * (NG * NH) + g * NH + c];
            const float hnew = (1.f - uu) * nn + uu * hold;
            hout[b * (NG * NH) + g * NH + c] = hnew;
            out[(size_t)(b * NT + t) * (NG * NH) + g * NH + c] = hnew;
        }
    }
}

// ---------------------------------------------------------------------------
// Launch: init h, one big projection GEMM, then 64 fused recurrent steps.
// All launches on the capture stream; no sync, no alloc.
// ---------------------------------------------------------------------------
extern "C" void kernel_launch(void* const* d_in, const int* in_sizes, int n_in,
                              void* d_out, int out_size) {
    const float* z   = (const float*)d_in[0];
    const float* a   = (const float*)d_in[1];
    const float* h   = (const float*)d_in[2];
    const float* Wih = (const float*)d_in[3];
    const float* Whh = (const float*)d_in[4];
    const float* bih = (const float*)d_in[5];
    const float* bhh = (const float*)d_in[6];
    float* out = (float*)d_out;

    init_h<<<(NB * NG * NH + 255) / 256, 256>>>(h);

    dim3 grid(NTOT / 128, MTOT / 128);   // (96, 64)
    xproj_gemm<<<grid, 256>>>(z, a, Wih, bih);

    for (int t = 0; t < NT; ++t)
        gru_step<<<128, 256>>>(Whh, bhh, out, t);
}

// round 3
// speedup vs baseline: 1.8163x; 1.8163x over previous
#include <cuda_runtime.h>
#include <stdint.h>
#include <math.h>

// Problem constants
#define NG   8
#define NH   512
#define NI   1028
#define KP   1040        // K padded to multiple of 16
#define NB   128
#define NT   64
#define N3H  1536
#define NTOT (NG*N3H)    // 12288
#define MTOT (NB*NT)     // 8192
#define GH   (NG*NH)     // 4096

// Scratch (__device__ globals: allocation-free rule)
__device__ float g_X[(size_t)MTOT * KP];      // packed tf32 concat(a,z), 34MB
__device__ float g_W[(size_t)NTOT * KP];      // packed tf32 W_ih, 51MB
__device__ float g_xproj[(size_t)MTOT * NTOT];// (B*T, G*3H), 402MB
__device__ float g_h[2][NB * GH];             // hidden ping-pong

__device__ __forceinline__ uint32_t to_tf32(float x) {
    uint32_t r;
    asm("cvt.rna.tf32.f32 %0, %1;" : "=r"(r) : "f"(x));
    return r;
}

__device__ __forceinline__ void mma_tf32(float* c, const uint32_t* a, const uint32_t* b) {
    asm volatile(
        "mma.sync.aligned.m16n8k8.row.col.f32.tf32.tf32.f32 "
        "{%0,%1,%2,%3}, {%4,%5,%6,%7}, {%8,%9}, {%0,%1,%2,%3};"
        : "+f"(c[0]), "+f"(c[1]), "+f"(c[2]), "+f"(c[3])
        : "r"(a[0]), "r"(a[1]), "r"(a[2]), "r"(a[3]), "r"(b[0]), "r"(b[1]));
}

// ---------------------------------------------------------------------------
__global__ void init_h(const float* __restrict__ h0) {
    int i = blockIdx.x * blockDim.x + threadIdx.x;
    if (i < NB * GH) g_h[0][i] = h0[i];
}

// Pack X = concat(a, z) into [MTOT, KP], tf32-rounded, zero-padded.
__global__ void pack_x(const float* __restrict__ z, const float* __restrict__ a) {
    int idx = blockIdx.x * blockDim.x + threadIdx.x;
    if (idx >= MTOT * KP) return;
    int m = idx / KP, k = idx % KP;
    float v = 0.f;
    if (k < 4)       v = a[m * 4 + k];
    else if (k < NI) v = z[(size_t)m * 1024 + (k - 4)];
    g_X[idx] = __uint_as_float(to_tf32(v));
}

// Pack W_ih into [NTOT, KP], tf32-rounded, zero-padded.
__global__ void pack_w(const float* __restrict__ Wih) {
    int idx = blockIdx.x * blockDim.x + threadIdx.x;
    if (idx >= NTOT * KP) return;
    int n = idx / KP, k = idx % KP;
    float v = (k < NI) ? Wih[(size_t)n * NI + k] : 0.f;
    g_W[idx] = __uint_as_float(to_tf32(v));
}

// ---------------------------------------------------------------------------
// xproj = X @ W^T + b : tf32 mma.sync, 128x128 CTA tile, K-tile 16,
// 8 warps (2x4), warp tile 64x32 (4x4 m16n8k8), double-buffered smem.
// ---------------------------------------------------------------------------
__global__ __launch_bounds__(256) void xproj_mma(const float* __restrict__ bih) {
    __shared__ float As[2][16][132];
    __shared__ float Bs[2][16][132];

    const int tid  = threadIdx.x;
    const int m0   = blockIdx.y * 128;
    const int n0   = blockIdx.x * 128;
    const int warp = tid >> 5, lane = tid & 31;
    const int wm   = (warp & 1) * 64;
    const int wn   = (warp >> 1) * 32;
    const int grp  = lane >> 2, tg = lane & 3;

    float c[4][4][4] = {};
    float4 ra[2], rb[2];

    auto loadG = [&](int kt) {
        #pragma unroll
        for (int u = 0; u < 2; ++u) {
            int id = tid + u * 256;
            int row = id >> 2, kq = id & 3;
            ra[u] = *(const float4*)&g_X[(size_t)(m0 + row) * KP + kt * 16 + kq * 4];
            rb[u] = *(const float4*)&g_W[(size_t)(n0 + row) * KP + kt * 16 + kq * 4];
        }
    };
    auto storeS = [&](int buf) {
        #pragma unroll
        for (int u = 0; u < 2; ++u) {
            int id = tid + u * 256;
            int row = id >> 2, kq = id & 3;
            As[buf][kq * 4 + 0][row] = ra[u].x;
            As[buf][kq * 4 + 1][row] = ra[u].y;
            As[buf][kq * 4 + 2][row] = ra[u].z;
            As[buf][kq * 4 + 3][row] = ra[u].w;
            Bs[buf][kq * 4 + 0][row] = rb[u].x;
            Bs[buf][kq * 4 + 1][row] = rb[u].y;
            Bs[buf][kq * 4 + 2][row] = rb[u].z;
            Bs[buf][kq * 4 + 3][row] = rb[u].w;
        }
    };

    const int KT = KP / 16;   // 65
    loadG(0);
    storeS(0);
    __syncthreads();

    for (int kt = 0; kt < KT; ++kt) {
        const int buf = kt & 1;
        if (kt + 1 < KT) loadG(kt + 1);

        #pragma unroll
        for (int ks = 0; ks < 2; ++ks) {
            const int k0 = ks * 8;
            uint32_t af[4][4], bf[4][2];
            #pragma unroll
            for (int i = 0; i < 4; ++i) {
                const int mr = wm + i * 16 + grp;
                af[i][0] = __float_as_uint(As[buf][k0 + tg    ][mr]);
                af[i][1] = __float_as_uint(As[buf][k0 + tg    ][mr + 8]);
                af[i][2] = __float_as_uint(As[buf][k0 + 4 + tg][mr]);
                af[i][3] = __float_as_uint(As[buf][k0 + 4 + tg][mr + 8]);
            }
            #pragma unroll
            for (int j = 0; j < 4; ++j) {
                const int nc = wn + j * 8 + grp;
                bf[j][0] = __float_as_uint(Bs[buf][k0 + tg    ][nc]);
                bf[j][1] = __float_as_uint(Bs[buf][k0 + 4 + tg][nc]);
            }
            #pragma unroll
            for (int i = 0; i < 4; ++i)
                #pragma unroll
                for (int j = 0; j < 4; ++j)
                    mma_tf32(c[i][j], af[i], bf[j]);
        }

        if (kt + 1 < KT) storeS(1 - buf);
        __syncthreads();
    }

    // Epilogue: += bias, store float2 pairs
    #pragma unroll
    for (int j = 0; j < 4; ++j) {
        const int col = n0 + wn + j * 8 + tg * 2;
        const float b0v = bih[col], b1v = bih[col + 1];
        #pragma unroll
        for (int i = 0; i < 4; ++i) {
            const int r0 = m0 + wm + i * 16 + grp;
            float2 v0 = make_float2(c[i][j][0] + b0v, c[i][j][1] + b1v);
            float2 v1 = make_float2(c[i][j][2] + b0v, c[i][j][3] + b1v);
            *(float2*)&g_xproj[(size_t)r0 * NTOT + col]       = v0;
            *(float2*)&g_xproj[(size_t)(r0 + 8) * NTOT + col] = v1;
        }
    }
}

// ---------------------------------------------------------------------------
// One GRU timestep (fp32 SIMT, fused gates). Batch-split: each CTA handles
// 64 batch rows x 32 H-cols x 3 gates of one block g. Grid = 8*16*2 = 256.
// Gate-aligned accumulators: {r,z,n} for a (b,c) live in one thread.
// ---------------------------------------------------------------------------
__global__ __launch_bounds__(256) void gru_step(
    const float* __restrict__ Whh, const float* __restrict__ bhh,
    float* __restrict__ out, int t)
{
    __shared__ float As[8][64];   // h tile [k][batch]
    __shared__ float Bs[8][96];   // W tile [k][3 gates x 32 cols]

    const float* __restrict__ hin  = g_h[t & 1];
    float* __restrict__       hout = g_h[(t + 1) & 1];

    const int tid  = threadIdx.x;
    const int g    = blockIdx.x >> 5;
    const int rest = blockIdx.x & 31;
    const int c0   = (rest >> 1) * 32;
    const int m0   = (rest & 1) * 64;
    const int tx   = tid & 15, ty = tid >> 4;

    float acc[4][6] = {};

    const int amm = tid >> 2;          // 0..63
    const int akb = (tid & 3) * 2;     // 0,2,4,6
    const int ca  = tx * 2, cb = ca + 1;

    for (int kc = 0; kc < 64; ++kc) {  // K = 512
        const int k0 = kc * 8;
        #pragma unroll
        for (int r = 0; r < 2; ++r)
            As[akb + r][amm] = hin[(m0 + amm) * GH + g * NH + k0 + akb + r];
        #pragma unroll
        for (int r = 0; r < 3; ++r) {
            const int idx = r * 256 + tid;       // 0..767
            const int kk = idx & 7, cc = idx >> 3;
            const int wrow = g * N3H + (cc >> 5) * NH + c0 + (cc & 31);
            Bs[kk][cc] = Whh[(size_t)wrow * NH + k0 + kk];
        }
        __syncthreads();
        #pragma unroll
        for (int kk = 0; kk < 8; ++kk) {
            float4 a0 = *(const float4*)&As[kk][ty * 4];
            float av[4] = {a0.x, a0.y, a0.z, a0.w};
            float bv[6];
            bv[0] = Bs[kk][ca];  bv[1] = Bs[kk][ca + 32];  bv[2] = Bs[kk][ca + 64];
            bv[3] = Bs[kk][cb];  bv[4] = Bs[kk][cb + 32];  bv[5] = Bs[kk][cb + 64];
            #pragma unroll
            for (int i = 0; i < 4; ++i)
                #pragma unroll
                for (int j = 0; j < 6; ++j)
                    acc[i][j] = fmaf(av[i], bv[j], acc[i][j]);
        }
        __syncthreads();
    }

    #pragma unroll
    for (int i = 0; i < 4; ++i) {
        const int b = m0 + ty * 4 + i;
        #pragma unroll
        for (int p = 0; p < 2; ++p) {
            const int c = c0 + tx * 2 + p;
            const float hr = acc[i][p * 3 + 0] + bhh[g * N3H + c];
            const float hz = acc[i][p * 3 + 1] + bhh[g * N3H + NH + c];
            const float hn = acc[i][p * 3 + 2] + bhh[g * N3H + 2 * NH + c];
            const size_t xb = (size_t)(b * NT + t) * NTOT + g * N3H;
            const float xr = g_xproj[xb + c];
            const float xz = g_xproj[xb + NH + c];
            const float xn = g_xproj[xb + 2 * NH + c];
            const float rr = 1.f / (1.f + __expf(-(xr + hr)));
            const float uu = 1.f / (1.f + __expf(-(xz + hz)));
            const float nn = tanhf(xn + rr * hn);
            const float hold = hin[b * GH + g * NH + c];
            const float hnew = (1.f - uu) * nn + uu * hold;
            hout[b * GH + g * NH + c] = hnew;
            out[(size_t)(b * NT + t) * GH + g * NH + c] = hnew;
        }
    }
}

// ---------------------------------------------------------------------------
extern "C" void kernel_launch(void* const* d_in, const int* in_sizes, int n_in,
                              void* d_out, int out_size) {
    const float* z   = (const float*)d_in[0];
    const float* a   = (const float*)d_in[1];
    const float* h   = (const float*)d_in[2];
    const float* Wih = (const float*)d_in[3];
    const float* Whh = (const float*)d_in[4];
    const float* bih = (const float*)d_in[5];
    const float* bhh = (const float*)d_in[6];
    float* out = (float*)d_out;

    init_h<<<(NB * GH + 255) / 256, 256>>>(h);
    pack_x<<<(MTOT * KP + 255) / 256, 256>>>(z, a);
    pack_w<<<(NTOT * KP + 255) / 256, 256>>>(Wih);

    dim3 grid(NTOT / 128, MTOT / 128);   // (96, 64)
    xproj_mma<<<grid, 256>>>(bih);

    for (int t = 0; t < NT; ++t)
        gru_step<<<256, 256>>>(Whh, bhh, out, t);
}

// round 4
// speedup vs baseline: 2.6180x; 1.4414x over previous
#include <cuda_runtime.h>
#include <stdint.h>
#include <math.h>

#define NG   8
#define NH   512
#define NI   1028
#define KP   1040
#define NB   128
#define NT   64
#define N3H  1536
#define NTOT (NG*N3H)    // 12288
#define MTOT (NB*NT)     // 8192
#define GH   (NG*NH)     // 4096

// Scratch (__device__ globals)
__device__ float g_X[(size_t)MTOT * KP];
__device__ float g_W[(size_t)NTOT * KP];
__device__ float g_xproj[(size_t)MTOT * NTOT];
__device__ float g_h[2][NB * GH];
__device__ int   g_sync[NG];

__device__ __forceinline__ uint32_t to_tf32(float x) {
    uint32_t r;
    asm("cvt.rna.tf32.f32 %0, %1;" : "=r"(r) : "f"(x));
    return r;
}

__device__ __forceinline__ void mma_tf32(float* c, const uint32_t* a, const uint32_t* b) {
    asm volatile(
        "mma.sync.aligned.m16n8k8.row.col.f32.tf32.tf32.f32 "
        "{%0,%1,%2,%3}, {%4,%5,%6,%7}, {%8,%9}, {%0,%1,%2,%3};"
        : "+f"(c[0]), "+f"(c[1]), "+f"(c[2]), "+f"(c[3])
        : "r"(a[0]), "r"(a[1]), "r"(a[2]), "r"(a[3]), "r"(b[0]), "r"(b[1]));
}

// ---------------------------------------------------------------------------
__global__ void init_h(const float* __restrict__ h0) {
    int i = blockIdx.x * blockDim.x + threadIdx.x;
    if (i < NB * GH) g_h[0][i] = h0[i];
    if (i < NG) g_sync[i] = 0;
}

__global__ void pack_x(const float* __restrict__ z, const float* __restrict__ a) {
    int idx = blockIdx.x * blockDim.x + threadIdx.x;
    if (idx >= MTOT * KP) return;
    int m = idx / KP, k = idx % KP;
    float v = 0.f;
    if (k < 4)       v = a[m * 4 + k];
    else if (k < NI) v = z[(size_t)m * 1024 + (k - 4)];
    g_X[idx] = __uint_as_float(to_tf32(v));
}

__global__ void pack_w(const float* __restrict__ Wih) {
    int idx = blockIdx.x * blockDim.x + threadIdx.x;
    if (idx >= NTOT * KP) return;
    int n = idx / KP, k = idx % KP;
    float v = (k < NI) ? Wih[(size_t)n * NI + k] : 0.f;
    g_W[idx] = __uint_as_float(to_tf32(v));
}

// ---------------------------------------------------------------------------
// xproj = X @ W^T + b  (unchanged from R3: known-good)
// ---------------------------------------------------------------------------
__global__ __launch_bounds__(256) void xproj_mma(const float* __restrict__ bih) {
    __shared__ float As[2][16][132];
    __shared__ float Bs[2][16][132];

    const int tid  = threadIdx.x;
    const int m0   = blockIdx.y * 128;
    const int n0   = blockIdx.x * 128;
    const int warp = tid >> 5, lane = tid & 31;
    const int wm   = (warp & 1) * 64;
    const int wn   = (warp >> 1) * 32;
    const int grp  = lane >> 2, tg = lane & 3;

    float c[4][4][4] = {};
    float4 ra[2], rb[2];

    auto loadG = [&](int kt) {
        #pragma unroll
        for (int u = 0; u < 2; ++u) {
            int id = tid + u * 256;
            int row = id >> 2, kq = id & 3;
            ra[u] = *(const float4*)&g_X[(size_t)(m0 + row) * KP + kt * 16 + kq * 4];
            rb[u] = *(const float4*)&g_W[(size_t)(n0 + row) * KP + kt * 16 + kq * 4];
        }
    };
    auto storeS = [&](int buf) {
        #pragma unroll
        for (int u = 0; u < 2; ++u) {
            int id = tid + u * 256;
            int row = id >> 2, kq = id & 3;
            As[buf][kq * 4 + 0][row] = ra[u].x;
            As[buf][kq * 4 + 1][row] = ra[u].y;
            As[buf][kq * 4 + 2][row] = ra[u].z;
            As[buf][kq * 4 + 3][row] = ra[u].w;
            Bs[buf][kq * 4 + 0][row] = rb[u].x;
            Bs[buf][kq * 4 + 1][row] = rb[u].y;
            Bs[buf][kq * 4 + 2][row] = rb[u].z;
            Bs[buf][kq * 4 + 3][row] = rb[u].w;
        }
    };

    const int KT = KP / 16;
    loadG(0);
    storeS(0);
    __syncthreads();

    for (int kt = 0; kt < KT; ++kt) {
        const int buf = kt & 1;
        if (kt + 1 < KT) loadG(kt + 1);

        #pragma unroll
        for (int ks = 0; ks < 2; ++ks) {
            const int k0 = ks * 8;
            uint32_t af[4][4], bf[4][2];
            #pragma unroll
            for (int i = 0; i < 4; ++i) {
                const int mr = wm + i * 16 + grp;
                af[i][0] = __float_as_uint(As[buf][k0 + tg    ][mr]);
                af[i][1] = __float_as_uint(As[buf][k0 + tg    ][mr + 8]);
                af[i][2] = __float_as_uint(As[buf][k0 + 4 + tg][mr]);
                af[i][3] = __float_as_uint(As[buf][k0 + 4 + tg][mr + 8]);
            }
            #pragma unroll
            for (int j = 0; j < 4; ++j) {
                const int nc = wn + j * 8 + grp;
                bf[j][0] = __float_as_uint(Bs[buf][k0 + tg    ][nc]);
                bf[j][1] = __float_as_uint(Bs[buf][k0 + 4 + tg][nc]);
            }
            #pragma unroll
            for (int i = 0; i < 4; ++i)
                #pragma unroll
                for (int j = 0; j < 4; ++j)
                    mma_tf32(c[i][j], af[i], bf[j]);
        }

        if (kt + 1 < KT) storeS(1 - buf);
        __syncthreads();
    }

    #pragma unroll
    for (int j = 0; j < 4; ++j) {
        const int col = n0 + wn + j * 8 + tg * 2;
        const float b0v = bih[col], b1v = bih[col + 1];
        #pragma unroll
        for (int i = 0; i < 4; ++i) {
            const int r0 = m0 + wm + i * 16 + grp;
            float2 v0 = make_float2(c[i][j][0] + b0v, c[i][j][1] + b1v);
            float2 v1 = make_float2(c[i][j][2] + b0v, c[i][j][3] + b1v);
            *(float2*)&g_xproj[(size_t)r0 * NTOT + col]       = v0;
            *(float2*)&g_xproj[(size_t)(r0 + 8) * NTOT + col] = v1;
        }
    }
}

// ---------------------------------------------------------------------------
// Persistent recurrence: one launch, 128 CTAs = (g, 32-col chunk).
// Whh chunk (96 rows x 512) lives in smem (tf32, k-interleaved) for all 64
// steps. Per step: hp = h @ W^T on tensor cores (tf32 + h-residual
// compensation), gate-aligned epilogue, h exchanged via L2 with a 16-CTA
// per-group atomic barrier.
// Warp layout: 8 warps x m16, each warp computes all 96 N (12 n-frags) so
// r/z/n for (b,c) sit in the same thread.
// ---------------------------------------------------------------------------
#define WS_PAD 520
#define AS_PAD 132
#define SMEM_PERS ((96*WS_PAD + 2*16*AS_PAD) * 4)

__global__ __launch_bounds__(256) void gru_persistent(
    const float* __restrict__ Whh, const float* __restrict__ bhh,
    float* __restrict__ out)
{
    extern __shared__ float sm[];
    float* Ws = sm;                         // [96][520]
    float* Asm = sm + 96 * WS_PAD;          // [2][16][132]

    const int tid  = threadIdx.x;
    const int g    = blockIdx.x >> 4;
    const int c0   = (blockIdx.x & 15) * 32;
    const int warp = tid >> 5, lane = tid & 31;
    const int grp  = lane >> 2, tg = lane & 3;
    const int wm   = warp * 16;             // batch-row base for this warp

    // ---- Fill Ws once: tf32-rounded, rows = gate*32+c_local, k-interleaved
    for (int idx = tid; idx < 96 * 512; idx += 256) {
        const int n = idx >> 9, k = idx & 511;
        const int gate = n >> 5, cl = n & 31;
        const float v = Whh[(size_t)(g * N3H + gate * NH + c0 + cl) * NH + k];
        const int kp = (k & ~7) + ((k & 3) << 1) + ((k >> 2) & 1);
        Ws[n * WS_PAD + kp] = __uint_as_float(to_tf32(v));
    }

    // ---- Per-thread biases (loop-invariant)
    float bias[3][4][2];
    #pragma unroll
    for (int gate = 0; gate < 3; ++gate)
        #pragma unroll
        for (int j = 0; j < 4; ++j) {
            bias[gate][j][0] = bhh[g * N3H + gate * NH + c0 + j * 8 + 2 * tg];
            bias[gate][j][1] = bhh[g * N3H + gate * NH + c0 + j * 8 + 2 * tg + 1];
        }
    __syncthreads();

    const int ldrow = tid >> 2;        // 0..63 (+64 on u=1)
    const int ldq   = tid & 3;         // float4 quad
    const int kpo   = (((ldq & 2) << 2)) + (ldq & 1);  // base kpos bits from quad

    for (int t = 0; t < NT; ++t) {
        const float* __restrict__ hin  = g_h[t & 1];
        float* __restrict__       hout = g_h[(t + 1) & 1];

        // ---- Prefetch x, h_old for epilogue (independent of MMA)
        float2 xv[3][4][2];
        float2 hv[4][2];
        #pragma unroll
        for (int j = 0; j < 4; ++j)
            #pragma unroll
            for (int r = 0; r < 2; ++r) {
                const int row = wm + grp + r * 8;
                const int col = c0 + j * 8 + 2 * tg;
                hv[j][r] = __ldcg((const float2*)&hin[row * GH + g * NH + col]);
                const size_t xb = (size_t)(row * NT + t) * NTOT + g * N3H;
                #pragma unroll
                for (int gate = 0; gate < 3; ++gate)
                    xv[gate][j][r] = *(const float2*)&g_xproj[xb + gate * NH + col];
            }

        float acc[12][4] = {};

        // ---- stage k-tile 0
        {
            #pragma unroll
            for (int u = 0; u < 2; ++u) {
                const int row = ldrow + u * 64;
                float4 v = __ldcg((const float4*)&hin[row * GH + g * NH + ldq * 4]);
                Asm[(kpo + 0) * AS_PAD + row] = v.x;
                Asm[(kpo + 2) * AS_PAD + row] = v.y;
                Asm[(kpo + 4) * AS_PAD + row] = v.z;
                Asm[(kpo + 6) * AS_PAD + row] = v.w;
            }
        }
        __syncthreads();

        for (int kc = 0; kc < 32; ++kc) {
            const int buf = kc & 1;
            float4 nx[2];
            if (kc < 31) {
                #pragma unroll
                for (int u = 0; u < 2; ++u) {
                    const int row = ldrow + u * 64;
                    nx[u] = __ldcg((const float4*)&hin[row * GH + g * NH + (kc + 1) * 16 + ldq * 4]);
                }
            }

            #pragma unroll
            for (int ks = 0; ks < 2; ++ks) {
                const float* ab = &Asm[(size_t)buf * (16 * AS_PAD) + (ks * 8 + 2 * tg) * AS_PAD];
                const float a00 = ab[wm + grp];              // (grp,   tg)
                const float a10 = ab[wm + grp + 8];          // (grp+8, tg)
                const float a01 = ab[AS_PAD + wm + grp];     // (grp,   tg+4)
                const float a11 = ab[AS_PAD + wm + grp + 8]; // (grp+8, tg+4)
                uint32_t ah[4], al[4];
                ah[0] = to_tf32(a00); al[0] = to_tf32(a00 - __uint_as_float(ah[0]));
                ah[1] = to_tf32(a10); al[1] = to_tf32(a10 - __uint_as_float(ah[1]));
                ah[2] = to_tf32(a01); al[2] = to_tf32(a01 - __uint_as_float(ah[2]));
                ah[3] = to_tf32(a11); al[3] = to_tf32(a11 - __uint_as_float(ah[3]));

                const int kcol = kc * 16 + ks * 8 + 2 * tg;
                #pragma unroll
                for (int jn = 0; jn < 12; ++jn) {
                    float2 b2 = *(const float2*)&Ws[(jn * 8 + grp) * WS_PAD + kcol];
                    uint32_t b[2] = {__float_as_uint(b2.x), __float_as_uint(b2.y)};
                    mma_tf32(acc[jn], ah, b);
                    mma_tf32(acc[jn], al, b);
                }
            }

            if (kc < 31) {
                const int ob = (buf ^ 1) * (16 * AS_PAD);
                #pragma unroll
                for (int u = 0; u < 2; ++u) {
                    const int row = ldrow + u * 64;
                    Asm[ob + (kpo + 0) * AS_PAD + row] = nx[u].x;
                    Asm[ob + (kpo + 2) * AS_PAD + row] = nx[u].y;
                    Asm[ob + (kpo + 4) * AS_PAD + row] = nx[u].z;
                    Asm[ob + (kpo + 6) * AS_PAD + row] = nx[u].w;
                }
            }
            __syncthreads();
        }

        // ---- Gate epilogue (gate-aligned: acc[j], acc[j+4], acc[j+8])
        #pragma unroll
        for (int j = 0; j < 4; ++j)
            #pragma unroll
            for (int r = 0; r < 2; ++r) {
                const int row = wm + grp + r * 8;
                const int col = c0 + j * 8 + 2 * tg;
                float2 hn2;
                #pragma unroll
                for (int p = 0; p < 2; ++p) {
                    const float hr = acc[j    ][r * 2 + p] + bias[0][j][p];
                    const float hz = acc[j + 4][r * 2 + p] + bias[1][j][p];
                    const float hnv= acc[j + 8][r * 2 + p] + bias[2][j][p];
                    const float xr = p ? xv[0][j][r].y : xv[0][j][r].x;
                    const float xz = p ? xv[1][j][r].y : xv[1][j][r].x;
                    const float xn = p ? xv[2][j][r].y : xv[2][j][r].x;
                    const float ho = p ? hv[j][r].y : hv[j][r].x;
                    const float rr = 1.f / (1.f + __expf(-(xr + hr)));
                    const float uu = 1.f / (1.f + __expf(-(xz + hz)));
                    const float nn = tanhf(xn + rr * hnv);
                    const float hw = (1.f - uu) * nn + uu * ho;
                    if (p == 0) hn2.x = hw; else hn2.y = hw;
                }
                *(float2*)&hout[row * GH + g * NH + col] = hn2;
                *(float2*)&out[(size_t)(row * NT + t) * GH + g * NH + col] = hn2;
            }

        // ---- group barrier: 16 CTAs of block g
        __threadfence();
        __syncthreads();
        if (tid == 0) {
            atomicAdd(&g_sync[g], 1);
            const int target = 16 * (t + 1);
            while (*(volatile int*)&g_sync[g] < target) { __nanosleep(64); }
        }
        __syncthreads();
    }
}

// ---------------------------------------------------------------------------
extern "C" void kernel_launch(void* const* d_in, const int* in_sizes, int n_in,
                              void* d_out, int out_size) {
    const float* z   = (const float*)d_in[0];
    const float* a   = (const float*)d_in[1];
    const float* h   = (const float*)d_in[2];
    const float* Wih = (const float*)d_in[3];
    const float* Whh = (const float*)d_in[4];
    const float* bih = (const float*)d_in[5];
    const float* bhh = (const float*)d_in[6];
    float* out = (float*)d_out;

    init_h<<<(NB * GH + 255) / 256, 256>>>(h);
    pack_x<<<(MTOT * KP + 255) / 256, 256>>>(z, a);
    pack_w<<<(NTOT * KP + 255) / 256, 256>>>(Wih);

    dim3 grid(NTOT / 128, MTOT / 128);
    xproj_mma<<<grid, 256>>>(bih);

    cudaFuncSetAttribute(gru_persistent,
                         cudaFuncAttributeMaxDynamicSharedMemorySize, SMEM_PERS);
    gru_persistent<<<128, 256, SMEM_PERS>>>(Whh, bhh, out);
}

// round 6
// speedup vs baseline: 2.8158x; 1.0755x over previous
#include <cuda_runtime.h>
#include <cuda_bf16.h>
#include <stdint.h>
#include <math.h>

#define NG   8
#define NH   512
#define NI   1028
#define NB   128
#define NT   64
#define N3H  1536
#define NTOT (NG*N3H)    // 12288
#define MTOT (NB*NT)     // 8192
#define GH   (NG*NH)     // 4096

// bf16 xproj geometry
#define KPC  1056        // K padded to 33 * 32
#define KT32 33          // k-tiles of 32

// ---- global scratch (__device__: allocation-free rule) ----
__device__ __nv_bfloat16 g_Xh[(size_t)MTOT * KPC];
__device__ __nv_bfloat16 g_Xl[(size_t)MTOT * KPC];
__device__ __nv_bfloat16 g_Wh[(size_t)NTOT * KPC];
__device__ __nv_bfloat16 g_Wl[(size_t)NTOT * KPC];
__device__ float g_xproj[(size_t)MTOT * NTOT];
__device__ float g_h[2][NB * GH];
__device__ int   g_sync[NG];

// ---- helpers ----
__device__ __forceinline__ uint32_t to_tf32(float x) {
    uint32_t r; asm("cvt.rna.tf32.f32 %0, %1;" : "=r"(r) : "f"(x)); return r;
}
__device__ __forceinline__ void mma_tf32(float* c, const uint32_t* a, const uint32_t* b) {
    asm volatile(
        "mma.sync.aligned.m16n8k8.row.col.f32.tf32.tf32.f32 "
        "{%0,%1,%2,%3}, {%4,%5,%6,%7}, {%8,%9}, {%0,%1,%2,%3};"
        : "+f"(c[0]), "+f"(c[1]), "+f"(c[2]), "+f"(c[3])
        : "r"(a[0]), "r"(a[1]), "r"(a[2]), "r"(a[3]), "r"(b[0]), "r"(b[1]));
}
__device__ __forceinline__ void mma_bf16(float* c, const uint32_t* a, const uint32_t* b) {
    asm volatile(
        "mma.sync.aligned.m16n8k16.row.col.f32.bf16.bf16.f32 "
        "{%0,%1,%2,%3}, {%4,%5,%6,%7}, {%8,%9}, {%0,%1,%2,%3};"
        : "+f"(c[0]), "+f"(c[1]), "+f"(c[2]), "+f"(c[3])
        : "r"(a[0]), "r"(a[1]), "r"(a[2]), "r"(a[3]), "r"(b[0]), "r"(b[1]));
}
__device__ __forceinline__ void ldsm4(uint32_t* r, uint32_t addr) {
    asm volatile("ldmatrix.sync.aligned.m8n8.x4.shared.b16 {%0,%1,%2,%3}, [%4];"
                 : "=r"(r[0]), "=r"(r[1]), "=r"(r[2]), "=r"(r[3]) : "r"(addr));
}
__device__ __forceinline__ uint32_t smem_u32(const void* p) {
    uint32_t a;
    asm("{ .reg .u64 t; cvta.to.shared.u64 t, %1; cvt.u32.u64 %0, t; }" : "=r"(a) : "l"(p));
    return a;
}
__device__ __forceinline__ void cp16(uint32_t dst, const void* src) {
    asm volatile("cp.async.cg.shared.global [%0], [%1], 16;" :: "r"(dst), "l"(src));
}
#define CP_COMMIT()  asm volatile("cp.async.commit_group;" ::: "memory")
#define CP_WAIT(n)   asm volatile("cp.async.wait_group %0;" :: "n"(n) : "memory")

// ---------------------------------------------------------------------------
__global__ void init_h(const float* __restrict__ h0) {
    int i = blockIdx.x * blockDim.x + threadIdx.x;
    if (i < NB * GH) g_h[0][i] = h0[i];
    if (i < NG) g_sync[i] = 0;
}

// Pack X = concat(a,z) -> bf16 hi/lo planes [MTOT][KPC]
__global__ void pack_x_bf16(const float* __restrict__ z, const float* __restrict__ a) {
    size_t idx = (size_t)blockIdx.x * blockDim.x + threadIdx.x;
    if (idx >= (size_t)MTOT * KPC) return;
    int m = (int)(idx / KPC), k = (int)(idx % KPC);
    float v = 0.f;
    if (k < 4)       v = a[m * 4 + k];
    else if (k < NI) v = z[(size_t)m * 1024 + (k - 4)];
    __nv_bfloat16 hi = __float2bfloat16(v);
    __nv_bfloat16 lo = __float2bfloat16(v - __bfloat162float(hi));
    g_Xh[idx] = hi;
    g_Xl[idx] = lo;
}

// Pack W_ih -> bf16 hi/lo planes [NTOT][KPC]
__global__ void pack_w_bf16(const float* __restrict__ Wih) {
    size_t idx = (size_t)blockIdx.x * blockDim.x + threadIdx.x;
    if (idx >= (size_t)NTOT * KPC) return;
    int n = (int)(idx / KPC), k = (int)(idx % KPC);
    float v = (k < NI) ? Wih[(size_t)n * NI + k] : 0.f;
    __nv_bfloat16 hi = __float2bfloat16(v);
    __nv_bfloat16 lo = __float2bfloat16(v - __bfloat162float(hi));
    g_Wh[idx] = hi;
    g_Wl[idx] = lo;
}

// ---------------------------------------------------------------------------
// xproj = X @ W^T + b, bf16 split (AhBh + AlBh + AhBl), fp32 accum.
// CTA 128x128, k-tile 32, double-buffered cp.async, ldmatrix operand loads.
// smem rows are 80B-strided (64B payload + 16B pad) => ldmatrix conflict-free.
// 8 warps = 2(m) x 4(n); warp tile 64x32 -> 4 m-frags x 4 n-frags.
// ---------------------------------------------------------------------------
#define ROWB   80
#define PLANE  (128 * ROWB)      // 10240 B: one operand plane per stage
#define STG    (4 * PLANE)       // 40960 B: Ah, Al, Bh, Bl
#define XS_SMEM (2 * STG)        // 81920 B

__global__ __launch_bounds__(256) void xproj_bf16(const float* __restrict__ bih) {
    extern __shared__ char smem[];
    const uint32_t sb = smem_u32(smem);
    const int tid = threadIdx.x, lane = tid & 31, warp = tid >> 5;
    const int m0 = blockIdx.y * 128, n0 = blockIdx.x * 128;
    const int wm = (warp & 1) * 64, wn = (warp >> 1) * 32;
    const int grp = lane >> 2, tg = lane & 3;

    float c[4][4][4] = {};

    auto stage = [&](int kt, int b) {
        const uint32_t dst0 = sb + b * STG;
        #pragma unroll
        for (int u = 0; u < 8; ++u) {
            const int i = tid + u * 256;          // 0..2047
            const int s = i >> 9;                 // operand plane
            const int r = (i >> 2) & 127;         // row
            const int ch = i & 3;                 // 16B chunk
            const char* src;
            if (s == 0)      src = (const char*)&g_Xh[(size_t)(m0 + r) * KPC];
            else if (s == 1) src = (const char*)&g_Xl[(size_t)(m0 + r) * KPC];
            else if (s == 2) src = (const char*)&g_Wh[(size_t)(n0 + r) * KPC];
            else             src = (const char*)&g_Wl[(size_t)(n0 + r) * KPC];
            cp16(dst0 + s * PLANE + r * ROWB + ch * 16, src + kt * 64 + ch * 16);
        }
        CP_COMMIT();
    };

    stage(0, 0);

    // per-lane ldmatrix source rows/offsets
    const int rowA = wm + (lane & 15);
    const int kAoff = (lane & 16) ? 16 : 0;
    const int rowB = wn + (lane & 7) + ((lane & 16) ? 8 : 0);
    const int kBoff = (lane & 8) ? 16 : 0;

    for (int kt = 0; kt < KT32; ++kt) {
        const int b = kt & 1;
        if (kt + 1 < KT32) { stage(kt + 1, b ^ 1); CP_WAIT(1); }
        else               { CP_WAIT(0); }
        __syncthreads();

        const uint32_t base = sb + b * STG;
        #pragma unroll
        for (int ks = 0; ks < 2; ++ks) {
            uint32_t ah[4][4], al[4][4], bh[4][2], bl[4][2];
            #pragma unroll
            for (int mi = 0; mi < 4; ++mi) {
                const uint32_t ad = base + (rowA + mi * 16) * ROWB + ks * 32 + kAoff;
                ldsm4(ah[mi], ad);
                ldsm4(al[mi], ad + PLANE);
            }
            #pragma unroll
            for (int np = 0; np < 2; ++np) {
                const uint32_t bd = base + 2 * PLANE + (rowB + np * 16) * ROWB + ks * 32 + kBoff;
                uint32_t t4[4];
                ldsm4(t4, bd);
                bh[np * 2][0] = t4[0]; bh[np * 2][1] = t4[1];
                bh[np * 2 + 1][0] = t4[2]; bh[np * 2 + 1][1] = t4[3];
                ldsm4(t4, bd + PLANE);
                bl[np * 2][0] = t4[0]; bl[np * 2][1] = t4[1];
                bl[np * 2 + 1][0] = t4[2]; bl[np * 2 + 1][1] = t4[3];
            }
            #pragma unroll
            for (int mi = 0; mi < 4; ++mi)
                #pragma unroll
                for (int nj = 0; nj < 4; ++nj) {
                    mma_bf16(c[mi][nj], ah[mi], bh[nj]);
                    mma_bf16(c[mi][nj], al[mi], bh[nj]);
                    mma_bf16(c[mi][nj], ah[mi], bl[nj]);
                }
        }
        __syncthreads();
    }

    // Epilogue: bias + store. c frag: rows grp/grp+8, cols 2tg,2tg+1.
    #pragma unroll
    for (int nj = 0; nj < 4; ++nj) {
        const int col = n0 + wn + nj * 8 + 2 * tg;
        const float b0v = bih[col], b1v = bih[col + 1];
        #pragma unroll
        for (int mi = 0; mi < 4; ++mi) {
            const int r0 = m0 + wm + mi * 16 + grp;
            float2 v0 = make_float2(c[mi][nj][0] + b0v, c[mi][nj][1] + b1v);
            float2 v1 = make_float2(c[mi][nj][2] + b0v, c[mi][nj][3] + b1v);
            *(float2*)&g_xproj[(size_t)r0 * NTOT + col]       = v0;
            *(float2*)&g_xproj[(size_t)(r0 + 8) * NTOT + col] = v1;
        }
    }
}

// ---------------------------------------------------------------------------
// Persistent recurrence (unchanged from R4 — proven correct & fast).
// ---------------------------------------------------------------------------
#define WS_PAD 520
#define AS_PAD 132
#define SMEM_PERS ((96*WS_PAD + 2*16*AS_PAD) * 4)

__global__ __launch_bounds__(256) void gru_persistent(
    const float* __restrict__ Whh, const float* __restrict__ bhh,
    float* __restrict__ out)
{
    extern __shared__ float sm[];
    float* Ws = sm;
    float* Asm = sm + 96 * WS_PAD;

    const int tid  = threadIdx.x;
    const int g    = blockIdx.x >> 4;
    const int c0   = (blockIdx.x & 15) * 32;
    const int warp = tid >> 5, lane = tid & 31;
    const int grp  = lane >> 2, tg = lane & 3;
    const int wm   = warp * 16;

    for (int idx = tid; idx < 96 * 512; idx += 256) {
        const int n = idx >> 9, k = idx & 511;
        const int gate = n >> 5, cl = n & 31;
        const float v = Whh[(size_t)(g * N3H + gate * NH + c0 + cl) * NH + k];
        const int kp = (k & ~7) + ((k & 3) << 1) + ((k >> 2) & 1);
        Ws[n * WS_PAD + kp] = __uint_as_float(to_tf32(v));
    }

    float bias[3][4][2];
    #pragma unroll
    for (int gate = 0; gate < 3; ++gate)
        #pragma unroll
        for (int j = 0; j < 4; ++j) {
            bias[gate][j][0] = bhh[g * N3H + gate * NH + c0 + j * 8 + 2 * tg];
            bias[gate][j][1] = bhh[g * N3H + gate * NH + c0 + j * 8 + 2 * tg + 1];
        }
    __syncthreads();

    const int ldrow = tid >> 2;
    const int ldq   = tid & 3;
    const int kpo   = (((ldq & 2) << 2)) + (ldq & 1);

    for (int t = 0; t < NT; ++t) {
        const float* __restrict__ hin  = g_h[t & 1];
        float* __restrict__       hout = g_h[(t + 1) & 1];

        float2 xv[3][4][2];
        float2 hv[4][2];
        #pragma unroll
        for (int j = 0; j < 4; ++j)
            #pragma unroll
            for (int r = 0; r < 2; ++r) {
                const int row = wm + grp + r * 8;
                const int col = c0 + j * 8 + 2 * tg;
                hv[j][r] = __ldcg((const float2*)&hin[row * GH + g * NH + col]);
                const size_t xb = (size_t)(row * NT + t) * NTOT + g * N3H;
                #pragma unroll
                for (int gate = 0; gate < 3; ++gate)
                    xv[gate][j][r] = *(const float2*)&g_xproj[xb + gate * NH + col];
            }

        float acc[12][4] = {};

        {
            #pragma unroll
            for (int u = 0; u < 2; ++u) {
                const int row = ldrow + u * 64;
                float4 v = __ldcg((const float4*)&hin[row * GH + g * NH + ldq * 4]);
                Asm[(kpo + 0) * AS_PAD + row] = v.x;
                Asm[(kpo + 2) * AS_PAD + row] = v.y;
                Asm[(kpo + 4) * AS_PAD + row] = v.z;
                Asm[(kpo + 6) * AS_PAD + row] = v.w;
            }
        }
        __syncthreads();

        for (int kc = 0; kc < 32; ++kc) {
            const int buf = kc & 1;
            float4 nx[2];
            if (kc < 31) {
                #pragma unroll
                for (int u = 0; u < 2; ++u) {
                    const int row = ldrow + u * 64;
                    nx[u] = __ldcg((const float4*)&hin[row * GH + g * NH + (kc + 1) * 16 + ldq * 4]);
                }
            }

            #pragma unroll
            for (int ks = 0; ks < 2; ++ks) {
                const float* ab = &Asm[(size_t)buf * (16 * AS_PAD) + (ks * 8 + 2 * tg) * AS_PAD];
                const float a00 = ab[wm + grp];
                const float a10 = ab[wm + grp + 8];
                const float a01 = ab[AS_PAD + wm + grp];
                const float a11 = ab[AS_PAD + wm + grp + 8];
                uint32_t ah[4], al[4];
                ah[0] = to_tf32(a00); al[0] = to_tf32(a00 - __uint_as_float(ah[0]));
                ah[1] = to_tf32(a10); al[1] = to_tf32(a10 - __uint_as_float(ah[1]));
                ah[2] = to_tf32(a01); al[2] = to_tf32(a01 - __uint_as_float(ah[2]));
                ah[3] = to_tf32(a11); al[3] = to_tf32(a11 - __uint_as_float(ah[3]));

                const int kcol = kc * 16 + ks * 8 + 2 * tg;
                #pragma unroll
                for (int jn = 0; jn < 12; ++jn) {
                    float2 b2 = *(const float2*)&Ws[(jn * 8 + grp) * WS_PAD + kcol];
                    uint32_t b[2] = {__float_as_uint(b2.x), __float_as_uint(b2.y)};
                    mma_tf32(acc[jn], ah, b);
                    mma_tf32(acc[jn], al, b);
                }
            }

            if (kc < 31) {
                const int ob = (buf ^ 1) * (16 * AS_PAD);
                #pragma unroll
                for (int u = 0; u < 2; ++u) {
                    const int row = ldrow + u * 64;
                    Asm[ob + (kpo + 0) * AS_PAD + row] = nx[u].x;
                    Asm[ob + (kpo + 2) * AS_PAD + row] = nx[u].y;
                    Asm[ob + (kpo + 4) * AS_PAD + row] = nx[u].z;
                    Asm[ob + (kpo + 6) * AS_PAD + row] = nx[u].w;
                }
            }
            __syncthreads();
        }

        #pragma unroll
        for (int j = 0; j < 4; ++j)
            #pragma unroll
            for (int r = 0; r < 2; ++r) {
                const int row = wm + grp + r * 8;
                const int col = c0 + j * 8 + 2 * tg;
                float2 hn2;
                #pragma unroll
                for (int p = 0; p < 2; ++p) {
                    const float hr = acc[j    ][r * 2 + p] + bias[0][j][p];
                    const float hz = acc[j + 4][r * 2 + p] + bias[1][j][p];
                    const float hnv= acc[j + 8][r * 2 + p] + bias[2][j][p];
                    const float xr = p ? xv[0][j][r].y : xv[0][j][r].x;
                    const float xz = p ? xv[1][j][r].y : xv[1][j][r].x;
                    const float xn = p ? xv[2][j][r].y : xv[2][j][r].x;
                    const float ho = p ? hv[j][r].y : hv[j][r].x;
                    const float rr = 1.f / (1.f + __expf(-(xr + hr)));
                    const float uu = 1.f / (1.f + __expf(-(xz + hz)));
                    const float nn = tanhf(xn + rr * hnv);
                    const float hw = (1.f - uu) * nn + uu * ho;
                    if (p == 0) hn2.x = hw; else hn2.y = hw;
                }
                *(float2*)&hout[row * GH + g * NH + col] = hn2;
                *(float2*)&out[(size_t)(row * NT + t) * GH + g * NH + col] = hn2;
            }

        __threadfence();
        __syncthreads();
        if (tid == 0) {
            atomicAdd(&g_sync[g], 1);
            const int target = 16 * (t + 1);
            while (*(volatile int*)&g_sync[g] < target) { __nanosleep(64); }
        }
        __syncthreads();
    }
}

// ---------------------------------------------------------------------------
extern "C" void kernel_launch(void* const* d_in, const int* in_sizes, int n_in,
                              void* d_out, int out_size) {
    const float* z   = (const float*)d_in[0];
    const float* a   = (const float*)d_in[1];
    const float* h   = (const float*)d_in[2];
    const float* Wih = (const float*)d_in[3];
    const float* Whh = (const float*)d_in[4];
    const float* bih = (const float*)d_in[5];
    const float* bhh = (const float*)d_in[6];
    float* out = (float*)d_out;

    init_h<<<(NB * GH + 255) / 256, 256>>>(h);

    {
        size_t nx = (size_t)MTOT * KPC;
        pack_x_bf16<<<(int)((nx + 255) / 256), 256>>>(z, a);
        size_t nw = (size_t)NTOT * KPC;
        pack_w_bf16<<<(int)((nw + 255) / 256), 256>>>(Wih);
    }

    cudaFuncSetAttribute(xproj_bf16, cudaFuncAttributeMaxDynamicSharedMemorySize, XS_SMEM);
    dim3 grid(NTOT / 128, MTOT / 128);   // (96, 64)
    xproj_bf16<<<grid, 256, XS_SMEM>>>(bih);

    cudaFuncSetAttribute(gru_persistent, cudaFuncAttributeMaxDynamicSharedMemorySize, SMEM_PERS);
    gru_persistent<<<128, 256, SMEM_PERS>>>(Whh, bhh, out);
}

// round 7
// speedup vs baseline: 3.9233x; 1.3933x over previous
#include <cuda_runtime.h>
#include <cuda_bf16.h>
#include <stdint.h>
#include <math.h>

#define NG   8
#define NH   512
#define NI   1028
#define NB   128
#define NT   64
#define N3H  1536
#define NTOT (NG*N3H)    // 12288
#define MTOT (NB*NT)     // 8192
#define GH   (NG*NH)     // 4096

// bf16 xproj geometry
#define KPC  1056        // K padded to 33 * 32
#define KT32 33          // k-tiles of 32

// ---- global scratch (__device__: allocation-free rule) ----
__device__ __nv_bfloat16 g_Xh[(size_t)MTOT * KPC];
__device__ __nv_bfloat16 g_Xl[(size_t)MTOT * KPC];
__device__ __nv_bfloat16 g_Wh[(size_t)NTOT * KPC];
__device__ __nv_bfloat16 g_Wl[(size_t)NTOT * KPC];
__device__ float g_xproj[(size_t)MTOT * NTOT];
__device__ float g_h[2][NB * GH];                  // fp32 h ping-pong
__device__ __nv_bfloat16 g_hb[2][2][NB * GH];      // bf16 hi/lo h planes
__device__ int   g_sync[NG];

// ---- helpers ----
__device__ __forceinline__ void mma_bf16(float* c, const uint32_t* a, const uint32_t* b) {
    asm volatile(
        "mma.sync.aligned.m16n8k16.row.col.f32.bf16.bf16.f32 "
        "{%0,%1,%2,%3}, {%4,%5,%6,%7}, {%8,%9}, {%0,%1,%2,%3};"
        : "+f"(c[0]), "+f"(c[1]), "+f"(c[2]), "+f"(c[3])
        : "r"(a[0]), "r"(a[1]), "r"(a[2]), "r"(a[3]), "r"(b[0]), "r"(b[1]));
}
__device__ __forceinline__ void ldsm4(uint32_t* r, uint32_t addr) {
    asm volatile("ldmatrix.sync.aligned.m8n8.x4.shared.b16 {%0,%1,%2,%3}, [%4];"
                 : "=r"(r[0]), "=r"(r[1]), "=r"(r[2]), "=r"(r[3]) : "r"(addr));
}
__device__ __forceinline__ uint32_t smem_u32(const void* p) {
    uint32_t a;
    asm("{ .reg .u64 t; cvta.to.shared.u64 t, %1; cvt.u32.u64 %0, t; }" : "=r"(a) : "l"(p));
    return a;
}
__device__ __forceinline__ void cp16(uint32_t dst, const void* src) {
    asm volatile("cp.async.cg.shared.global [%0], [%1], 16;" :: "r"(dst), "l"(src));
}
#define CP_COMMIT()  asm volatile("cp.async.commit_group;" ::: "memory")
#define CP_WAIT(n)   asm volatile("cp.async.wait_group %0;" :: "n"(n) : "memory")

// ---------------------------------------------------------------------------
__global__ void init_h(const float* __restrict__ h0) {
    int i = blockIdx.x * blockDim.x + threadIdx.x;
    if (i < NB * GH) {
        float v = h0[i];
        g_h[0][i] = v;
        __nv_bfloat16 hi = __float2bfloat16(v);
        g_hb[0][0][i] = hi;
        g_hb[0][1][i] = __float2bfloat16(v - __bfloat162float(hi));
    }
    if (i < NG) g_sync[i] = 0;
}

// Pack X = concat(a,z) -> bf16 hi/lo planes [MTOT][KPC]
__global__ void pack_x_bf16(const float* __restrict__ z, const float* __restrict__ a) {
    size_t idx = (size_t)blockIdx.x * blockDim.x + threadIdx.x;
    if (idx >= (size_t)MTOT * KPC) return;
    int m = (int)(idx / KPC), k = (int)(idx % KPC);
    float v = 0.f;
    if (k < 4)       v = a[m * 4 + k];
    else if (k < NI) v = z[(size_t)m * 1024 + (k - 4)];
    __nv_bfloat16 hi = __float2bfloat16(v);
    g_Xh[idx] = hi;
    g_Xl[idx] = __float2bfloat16(v - __bfloat162float(hi));
}

// Pack W_ih -> bf16 hi/lo planes [NTOT][KPC]
__global__ void pack_w_bf16(const float* __restrict__ Wih) {
    size_t idx = (size_t)blockIdx.x * blockDim.x + threadIdx.x;
    if (idx >= (size_t)NTOT * KPC) return;
    int n = (int)(idx / KPC), k = (int)(idx % KPC);
    float v = (k < NI) ? Wih[(size_t)n * NI + k] : 0.f;
    __nv_bfloat16 hi = __float2bfloat16(v);
    g_Wh[idx] = hi;
    g_Wl[idx] = __float2bfloat16(v - __bfloat162float(hi));
}

// ---------------------------------------------------------------------------
// xproj = X @ W^T + b  (unchanged from R6 — known-good, tensor-bound)
// ---------------------------------------------------------------------------
#define ROWB   80
#define PLANE  (128 * ROWB)
#define STG    (4 * PLANE)
#define XS_SMEM (2 * STG)

__global__ __launch_bounds__(256) void xproj_bf16(const float* __restrict__ bih) {
    extern __shared__ char smem[];
    const uint32_t sb = smem_u32(smem);
    const int tid = threadIdx.x, lane = tid & 31, warp = tid >> 5;
    const int m0 = blockIdx.y * 128, n0 = blockIdx.x * 128;
    const int wm = (warp & 1) * 64, wn = (warp >> 1) * 32;
    const int grp = lane >> 2, tg = lane & 3;

    float c[4][4][4] = {};

    auto stage = [&](int kt, int b) {
        const uint32_t dst0 = sb + b * STG;
        #pragma unroll
        for (int u = 0; u < 8; ++u) {
            const int i = tid + u * 256;
            const int s = i >> 9;
            const int r = (i >> 2) & 127;
            const int ch = i & 3;
            const char* src;
            if (s == 0)      src = (const char*)&g_Xh[(size_t)(m0 + r) * KPC];
            else if (s == 1) src = (const char*)&g_Xl[(size_t)(m0 + r) * KPC];
            else if (s == 2) src = (const char*)&g_Wh[(size_t)(n0 + r) * KPC];
            else             src = (const char*)&g_Wl[(size_t)(n0 + r) * KPC];
            cp16(dst0 + s * PLANE + r * ROWB + ch * 16, src + kt * 64 + ch * 16);
        }
        CP_COMMIT();
    };

    stage(0, 0);

    const int rowA = wm + (lane & 15);
    const int kAoff = (lane & 16) ? 16 : 0;
    const int rowB = wn + (lane & 7) + ((lane & 16) ? 8 : 0);
    const int kBoff = (lane & 8) ? 16 : 0;

    for (int kt = 0; kt < KT32; ++kt) {
        const int b = kt & 1;
        if (kt + 1 < KT32) { stage(kt + 1, b ^ 1); CP_WAIT(1); }
        else               { CP_WAIT(0); }
        __syncthreads();

        const uint32_t base = sb + b * STG;
        #pragma unroll
        for (int ks = 0; ks < 2; ++ks) {
            uint32_t ah[4][4], al[4][4], bh[4][2], bl[4][2];
            #pragma unroll
            for (int mi = 0; mi < 4; ++mi) {
                const uint32_t ad = base + (rowA + mi * 16) * ROWB + ks * 32 + kAoff;
                ldsm4(ah[mi], ad);
                ldsm4(al[mi], ad + PLANE);
            }
            #pragma unroll
            for (int np = 0; np < 2; ++np) {
                const uint32_t bd = base + 2 * PLANE + (rowB + np * 16) * ROWB + ks * 32 + kBoff;
                uint32_t t4[4];
                ldsm4(t4, bd);
                bh[np * 2][0] = t4[0]; bh[np * 2][1] = t4[1];
                bh[np * 2 + 1][0] = t4[2]; bh[np * 2 + 1][1] = t4[3];
                ldsm4(t4, bd + PLANE);
                bl[np * 2][0] = t4[0]; bl[np * 2][1] = t4[1];
                bl[np * 2 + 1][0] = t4[2]; bl[np * 2 + 1][1] = t4[3];
            }
            #pragma unroll
            for (int mi = 0; mi < 4; ++mi)
                #pragma unroll
                for (int nj = 0; nj < 4; ++nj) {
                    mma_bf16(c[mi][nj], ah[mi], bh[nj]);
                    mma_bf16(c[mi][nj], al[mi], bh[nj]);
                    mma_bf16(c[mi][nj], ah[mi], bl[nj]);
                }
        }
        __syncthreads();
    }

    #pragma unroll
    for (int nj = 0; nj < 4; ++nj) {
        const int col = n0 + wn + nj * 8 + 2 * tg;
        const float b0v = bih[col], b1v = bih[col + 1];
        #pragma unroll
        for (int mi = 0; mi < 4; ++mi) {
            const int r0 = m0 + wm + mi * 16 + grp;
            float2 v0 = make_float2(c[mi][nj][0] + b0v, c[mi][nj][1] + b1v);
            float2 v1 = make_float2(c[mi][nj][2] + b0v, c[mi][nj][3] + b1v);
            *(float2*)&g_xproj[(size_t)r0 * NTOT + col]       = v0;
            *(float2*)&g_xproj[(size_t)(r0 + 8) * NTOT + col] = v1;
        }
    }
}

// ---------------------------------------------------------------------------
// Persistent recurrence, bf16/ldmatrix edition.
// 128 CTAs = (g, 32-col chunk). Whh chunk pre-split into bf16 hi/lo planes in
// smem (rows = 96 gate-cols, 1040B stride) once. h arrives as bf16 hi/lo
// planes in global (written by prior step's epilogue), staged per k16 tile.
// 3-term compensated MMA: Ah*Bh + Al*Bh + Ah*Bl, fp32 accum, gate-aligned.
// ---------------------------------------------------------------------------
#define W_STRIDE 1040
#define W_PLANE  (96 * W_STRIDE)        // 99840
#define A_STRIDE 48
#define A_PLANE  (128 * A_STRIDE)       // 6144
#define A_BUF    (2 * A_PLANE)          // 12288
#define A_BASE   (2 * W_PLANE)          // 199680
#define SMEM_GRU (A_BASE + 2 * A_BUF)   // 224256

__global__ __launch_bounds__(256) void gru_persistent(
    const float* __restrict__ Whh, const float* __restrict__ bhh,
    float* __restrict__ out)
{
    extern __shared__ char sm[];
    const uint32_t sb = smem_u32(sm);

    const int tid  = threadIdx.x;
    const int g    = blockIdx.x >> 4;
    const int c0   = (blockIdx.x & 15) * 32;
    const int warp = tid >> 5, lane = tid & 31;
    const int grp  = lane >> 2, tg = lane & 3;
    const int wm   = warp * 16;

    // ---- Fill W hi/lo planes once (rows n = gate*32 + cl, cols k) ----
    for (int idx = tid; idx < 96 * 512; idx += 256) {
        const int n = idx >> 9, k = idx & 511;
        const float v = Whh[(size_t)(g * N3H + (n >> 5) * NH + c0 + (n & 31)) * NH + k];
        const __nv_bfloat16 hi = __float2bfloat16(v);
        *(__nv_bfloat16*)(sm + n * W_STRIDE + k * 2) = hi;
        *(__nv_bfloat16*)(sm + W_PLANE + n * W_STRIDE + k * 2) =
            __float2bfloat16(v - __bfloat162float(hi));
    }

    // ---- Loop-invariant biases ----
    float bias[3][4][2];
    #pragma unroll
    for (int gate = 0; gate < 3; ++gate)
        #pragma unroll
        for (int j = 0; j < 4; ++j) {
            bias[gate][j][0] = bhh[g * N3H + gate * NH + c0 + j * 8 + 2 * tg];
            bias[gate][j][1] = bhh[g * N3H + gate * NH + c0 + j * 8 + 2 * tg + 1];
        }
    __syncthreads();

    // ldmatrix source addressing (validated pattern from xproj)
    const uint32_t aoff = (wm + (lane & 15)) * A_STRIDE + ((lane & 16) ? 16 : 0);
    const int rB  = (lane & 7) + ((lane & 16) ? 8 : 0);
    const uint32_t bko = (lane & 8) ? 16 : 0;

    // staging ids: 2 chunks of 16B per thread per k16 tile
    const int sid0 = tid, sid1 = tid + 256;

    for (int t = 0; t < NT; ++t) {
        const __nv_bfloat16* __restrict__ hbh = g_hb[t & 1][0];
        const __nv_bfloat16* __restrict__ hbl = g_hb[t & 1][1];

        auto src_of = [&](int id, int kc) -> const uint4* {
            const int plane = id >> 8, rem = id & 255;
            const int row = rem >> 1, seg = rem & 1;
            const __nv_bfloat16* p = plane ? hbl : hbh;
            return (const uint4*)&p[row * GH + g * NH + kc * 16 + seg * 8];
        };
        auto dst_of = [&](int id, int buf) -> uint4* {
            const int plane = id >> 8, rem = id & 255;
            const int row = rem >> 1, seg = rem & 1;
            return (uint4*)(sm + A_BASE + buf * A_BUF + plane * A_PLANE
                            + row * A_STRIDE + seg * 16);
        };

        // stage k-tile 0 into buf 0
        *dst_of(sid0, 0) = __ldcg(src_of(sid0, 0));
        *dst_of(sid1, 0) = __ldcg(src_of(sid1, 0));
        __syncthreads();

        float acc[12][4] = {};

        for (int kc = 0; kc < 32; ++kc) {
            const int buf = kc & 1;
            uint4 nx0, nx1;
            if (kc < 31) {
                nx0 = __ldcg(src_of(sid0, kc + 1));
                nx1 = __ldcg(src_of(sid1, kc + 1));
            }

            uint32_t ah[4], al[4];
            const uint32_t ab = sb + A_BASE + buf * A_BUF + aoff;
            ldsm4(ah, ab);
            ldsm4(al, ab + A_PLANE);

            const uint32_t kb = kc * 32 + bko;
            #pragma unroll
            for (int jp = 0; jp < 6; ++jp) {
                uint32_t bh4[4], bl4[4];
                const uint32_t baddr = sb + (jp * 16 + rB) * W_STRIDE + kb;
                ldsm4(bh4, baddr);
                ldsm4(bl4, baddr + W_PLANE);
                mma_bf16(acc[jp * 2],     ah, bh4);
                mma_bf16(acc[jp * 2],     al, bh4);
                mma_bf16(acc[jp * 2],     ah, bl4);
                mma_bf16(acc[jp * 2 + 1], ah, bh4 + 2);
                mma_bf16(acc[jp * 2 + 1], al, bh4 + 2);
                mma_bf16(acc[jp * 2 + 1], ah, bl4 + 2);
            }

            if (kc < 31) {
                *dst_of(sid0, buf ^ 1) = nx0;
                *dst_of(sid1, buf ^ 1) = nx1;
            }
            __syncthreads();
        }

        // ---- Gate epilogue (acc[j]=reset, acc[j+4]=update, acc[j+8]=new) ----
        float* __restrict__ hout = g_h[(t + 1) & 1];
        const float* __restrict__ hin = g_h[t & 1];
        __nv_bfloat16* __restrict__ nbh = g_hb[(t + 1) & 1][0];
        __nv_bfloat16* __restrict__ nbl = g_hb[(t + 1) & 1][1];

        #pragma unroll
        for (int j = 0; j < 4; ++j)
            #pragma unroll
            for (int r = 0; r < 2; ++r) {
                const int row = wm + grp + r * 8;
                const int col = c0 + j * 8 + 2 * tg;
                const size_t hidx = (size_t)row * GH + g * NH + col;
                const size_t xb = (size_t)(row * NT + t) * NTOT + g * N3H;
                const float2 xr2 = *(const float2*)&g_xproj[xb + col];
                const float2 xz2 = *(const float2*)&g_xproj[xb + NH + col];
                const float2 xn2 = *(const float2*)&g_xproj[xb + 2 * NH + col];
                const float2 ho2 = __ldcg((const float2*)&hin[hidx]);
                float2 hn2;
                #pragma unroll
                for (int p = 0; p < 2; ++p) {
                    const float hr = acc[j    ][r * 2 + p] + bias[0][j][p];
                    const float hz = acc[j + 4][r * 2 + p] + bias[1][j][p];
                    const float hnv= acc[j + 8][r * 2 + p] + bias[2][j][p];
                    const float xr = p ? xr2.y : xr2.x;
                    const float xz = p ? xz2.y : xz2.x;
                    const float xn = p ? xn2.y : xn2.x;
                    const float ho = p ? ho2.y : ho2.x;
                    const float rr = 1.f / (1.f + __expf(-(xr + hr)));
                    const float uu = 1.f / (1.f + __expf(-(xz + hz)));
                    const float nn = tanhf(xn + rr * hnv);
                    const float hw = (1.f - uu) * nn + uu * ho;
                    if (p == 0) hn2.x = hw; else hn2.y = hw;
                }
                *(float2*)&hout[hidx] = hn2;
                __nv_bfloat162 h2;
                h2.x = __float2bfloat16(hn2.x);
                h2.y = __float2bfloat16(hn2.y);
                __nv_bfloat162 l2;
                l2.x = __float2bfloat16(hn2.x - __bfloat162float(h2.x));
                l2.y = __float2bfloat16(hn2.y - __bfloat162float(h2.y));
                *(__nv_bfloat162*)&nbh[hidx] = h2;
                *(__nv_bfloat162*)&nbl[hidx] = l2;
                *(float2*)&out[(size_t)(row * NT + t) * GH + g * NH + col] = hn2;
            }

        // ---- group barrier: 16 CTAs of block g ----
        __threadfence();
        __syncthreads();
        if (tid == 0) {
            atomicAdd(&g_sync[g], 1);
            const int target = 16 * (t + 1);
            while (*(volatile int*)&g_sync[g] < target) { __nanosleep(64); }
        }
        __syncthreads();
    }
}

// ---------------------------------------------------------------------------
extern "C" void kernel_launch(void* const* d_in, const int* in_sizes, int n_in,
                              void* d_out, int out_size) {
    const float* z   = (const float*)d_in[0];
    const float* a   = (const float*)d_in[1];
    const float* h   = (const float*)d_in[2];
    const float* Wih = (const float*)d_in[3];
    const float* Whh = (const float*)d_in[4];
    const float* bih = (const float*)d_in[5];
    const float* bhh = (const float*)d_in[6];
    float* out = (float*)d_out;

    init_h<<<(NB * GH + 255) / 256, 256>>>(h);

    {
        size_t nx = (size_t)MTOT * KPC;
        pack_x_bf16<<<(int)((nx + 255) / 256), 256>>>(z, a);
        size_t nw = (size_t)NTOT * KPC;
        pack_w_bf16<<<(int)((nw + 255) / 256), 256>>>(Wih);
    }

    cudaFuncSetAttribute(xproj_bf16, cudaFuncAttributeMaxDynamicSharedMemorySize, XS_SMEM);
    dim3 grid(NTOT / 128, MTOT / 128);
    xproj_bf16<<<grid, 256, XS_SMEM>>>(bih);

    cudaFuncSetAttribute(gru_persistent, cudaFuncAttributeMaxDynamicSharedMemorySize, SMEM_GRU);
    gru_persistent<<<128, 256, SMEM_GRU>>>(Whh, bhh, out);
}

// round 9
// speedup vs baseline: 6.4829x; 1.6524x over previous
#include <cuda_runtime.h>
#include <cuda_fp16.h>
#include <stdint.h>
#include <math.h>

#define NG   8
#define NH   512
#define NI   1028
#define NB   128
#define NT   64
#define N3H  1536
#define NTOT (NG*N3H)    // 12288
#define MTOT (NB*NT)     // 8192
#define GH   (NG*NH)     // 4096

// fp16 xproj geometry
#define KPC  1056        // K padded to 33 * 32
#define KT32 33          // k-tiles of 32

// ---- global scratch (__device__: allocation-free rule) ----
__device__ __half g_Xp[(size_t)MTOT * KPC];
__device__ __half g_Wp[(size_t)NTOT * KPC];
__device__ float  g_xproj[(size_t)MTOT * NTOT];
__device__ float  g_h[2][NB * GH];          // fp32 h ping-pong (exact path)
__device__ __half g_hh[2][NB * GH];         // fp16 h planes for MMA
__device__ int    g_sync[NG];

// ---- helpers ----
__device__ __forceinline__ void mma_f16(float* c, const uint32_t* a, const uint32_t* b) {
    asm volatile(
        "mma.sync.aligned.m16n8k16.row.col.f32.f16.f16.f32 "
        "{%0,%1,%2,%3}, {%4,%5,%6,%7}, {%8,%9}, {%0,%1,%2,%3};"
        : "+f"(c[0]), "+f"(c[1]), "+f"(c[2]), "+f"(c[3])
        : "r"(a[0]), "r"(a[1]), "r"(a[2]), "r"(a[3]), "r"(b[0]), "r"(b[1]));
}
__device__ __forceinline__ void ldsm4(uint32_t* r, uint32_t addr) {
    asm volatile("ldmatrix.sync.aligned.m8n8.x4.shared.b16 {%0,%1,%2,%3}, [%4];"
                 : "=r"(r[0]), "=r"(r[1]), "=r"(r[2]), "=r"(r[3]) : "r"(addr));
}
__device__ __forceinline__ uint32_t smem_u32(const void* p) {
    uint32_t a;
    asm("{ .reg .u64 t; cvta.to.shared.u64 t, %1; cvt.u32.u64 %0, t; }" : "=r"(a) : "l"(p));
    return a;
}
__device__ __forceinline__ void cp16(uint32_t dst, const void* src) {
    asm volatile("cp.async.cg.shared.global [%0], [%1], 16;" :: "r"(dst), "l"(src));
}
#define CP_COMMIT()  asm volatile("cp.async.commit_group;" ::: "memory")
#define CP_WAIT(n)   asm volatile("cp.async.wait_group %0;" :: "n"(n) : "memory")

// ---------------------------------------------------------------------------
__global__ void init_h(const float* __restrict__ h0) {
    int i = blockIdx.x * blockDim.x + threadIdx.x;
    if (i < NB * GH) {
        float v = h0[i];
        g_h[0][i]  = v;
        g_hh[0][i] = __float2half_rn(v);
    }
    if (i < NG) g_sync[i] = 0;
}

// Pack X = concat(a,z) -> fp16 plane [MTOT][KPC]
__global__ void pack_x_f16(const float* __restrict__ z, const float* __restrict__ a) {
    size_t idx = (size_t)blockIdx.x * blockDim.x + threadIdx.x;
    if (idx >= (size_t)MTOT * KPC) return;
    int m = (int)(idx / KPC), k = (int)(idx % KPC);
    float v = 0.f;
    if (k < 4)       v = a[m * 4 + k];
    else if (k < NI) v = z[(size_t)m * 1024 + (k - 4)];
    g_Xp[idx] = __float2half_rn(v);
}

// Pack W_ih -> fp16 plane [NTOT][KPC]
__global__ void pack_w_f16(const float* __restrict__ Wih) {
    size_t idx = (size_t)blockIdx.x * blockDim.x + threadIdx.x;
    if (idx >= (size_t)NTOT * KPC) return;
    int n = (int)(idx / KPC), k = (int)(idx % KPC);
    g_Wp[idx] = __float2half_rn((k < NI) ? Wih[(size_t)n * NI + k] : 0.f);
}

// ---------------------------------------------------------------------------
// xproj = X @ W^T + b, fp16 single-term, fp32 accum.
// CTA 128x128, k-tile 32, double-buffered cp.async, ldmatrix.
// ---------------------------------------------------------------------------
#define ROWB   80
#define PLANE  (128 * ROWB)      // 10240 B
#define STG    (2 * PLANE)       // A, B planes
#define XS_SMEM (2 * STG)        // 40960 B

__global__ __launch_bounds__(256) void xproj_f16(const float* __restrict__ bih) {
    extern __shared__ char smem[];
    const uint32_t sb = smem_u32(smem);
    const int tid = threadIdx.x, lane = tid & 31, warp = tid >> 5;
    const int m0 = blockIdx.y * 128, n0 = blockIdx.x * 128;
    const int wm = (warp & 1) * 64, wn = (warp >> 1) * 32;
    const int grp = lane >> 2, tg = lane & 3;

    float c[4][4][4] = {};

    auto stage = [&](int kt, int b) {
        const uint32_t dst0 = sb + b * STG;
        #pragma unroll
        for (int u = 0; u < 4; ++u) {
            const int i = tid + u * 256;          // 0..1023
            const int s = i >> 9;                 // plane: 0=A, 1=B
            const int r = (i >> 2) & 127;         // row
            const int ch = i & 3;                 // 16B chunk
            const char* src = s
                ? (const char*)&g_Wp[(size_t)(n0 + r) * KPC]
                : (const char*)&g_Xp[(size_t)(m0 + r) * KPC];
            cp16(dst0 + s * PLANE + r * ROWB + ch * 16, src + kt * 64 + ch * 16);
        }
        CP_COMMIT();
    };

    stage(0, 0);

    const int rowA = wm + (lane & 15);
    const int kAoff = (lane & 16) ? 16 : 0;
    const int rowB = wn + (lane & 7) + ((lane & 16) ? 8 : 0);
    const int kBoff = (lane & 8) ? 16 : 0;

    for (int kt = 0; kt < KT32; ++kt) {
        const int b = kt & 1;
        if (kt + 1 < KT32) { stage(kt + 1, b ^ 1); CP_WAIT(1); }
        else               { CP_WAIT(0); }
        __syncthreads();

        const uint32_t base = sb + b * STG;
        #pragma unroll
        for (int ks = 0; ks < 2; ++ks) {
            uint32_t ah[4][4], bh[4][2];
            #pragma unroll
            for (int mi = 0; mi < 4; ++mi)
                ldsm4(ah[mi], base + (rowA + mi * 16) * ROWB + ks * 32 + kAoff);
            #pragma unroll
            for (int np = 0; np < 2; ++np) {
                uint32_t t4[4];
                ldsm4(t4, base + PLANE + (rowB + np * 16) * ROWB + ks * 32 + kBoff);
                bh[np * 2][0] = t4[0]; bh[np * 2][1] = t4[1];
                bh[np * 2 + 1][0] = t4[2]; bh[np * 2 + 1][1] = t4[3];
            }
            #pragma unroll
            for (int mi = 0; mi < 4; ++mi)
                #pragma unroll
                for (int nj = 0; nj < 4; ++nj)
                    mma_f16(c[mi][nj], ah[mi], bh[nj]);
        }
        __syncthreads();
    }

    #pragma unroll
    for (int nj = 0; nj < 4; ++nj) {
        const int col = n0 + wn + nj * 8 + 2 * tg;
        const float b0v = bih[col], b1v = bih[col + 1];
        #pragma unroll
        for (int mi = 0; mi < 4; ++mi) {
            const int r0 = m0 + wm + mi * 16 + grp;
            float2 v0 = make_float2(c[mi][nj][0] + b0v, c[mi][nj][1] + b1v);
            float2 v1 = make_float2(c[mi][nj][2] + b0v, c[mi][nj][3] + b1v);
            *(float2*)&g_xproj[(size_t)r0 * NTOT + col]       = v0;
            *(float2*)&g_xproj[(size_t)(r0 + 8) * NTOT + col] = v1;
        }
    }
}

// ---------------------------------------------------------------------------
// Persistent recurrence, fp16/ldmatrix single-term.
// 128 CTAs = (g, 32-col chunk). Whh chunk as fp16 in smem once (96 rows,
// 1040B stride). h staged per k16 from global fp16 plane; fp32 h kept for
// the exact u*h_old path. Gate-aligned accumulators.
// ---------------------------------------------------------------------------
#define W_STRIDE 1040
#define W_PLANE  (96 * W_STRIDE)        // 99840
#define A_STRIDE 48
#define A_PLANE  (128 * A_STRIDE)       // 6144
#define A_BASE   W_PLANE
#define SMEM_GRU (A_BASE + 2 * A_PLANE) // 112128

__global__ __launch_bounds__(256) void gru_persistent(
    const float* __restrict__ Whh, const float* __restrict__ bhh,
    float* __restrict__ out)
{
    extern __shared__ char sm[];
    const uint32_t sb = smem_u32(sm);

    const int tid  = threadIdx.x;
    const int g    = blockIdx.x >> 4;
    const int c0   = (blockIdx.x & 15) * 32;
    const int warp = tid >> 5, lane = tid & 31;
    const int grp  = lane >> 2, tg = lane & 3;
    const int wm   = warp * 16;

    // ---- Fill W plane once (rows n = gate*32 + cl, cols k) ----
    for (int idx = tid; idx < 96 * 512; idx += 256) {
        const int n = idx >> 9, k = idx & 511;
        const float v = Whh[(size_t)(g * N3H + (n >> 5) * NH + c0 + (n & 31)) * NH + k];
        *(__half*)(sm + n * W_STRIDE + k * 2) = __float2half_rn(v);
    }

    // ---- Loop-invariant biases ----
    float bias[3][4][2];
    #pragma unroll
    for (int gate = 0; gate < 3; ++gate)
        #pragma unroll
        for (int j = 0; j < 4; ++j) {
            bias[gate][j][0] = bhh[g * N3H + gate * NH + c0 + j * 8 + 2 * tg];
            bias[gate][j][1] = bhh[g * N3H + gate * NH + c0 + j * 8 + 2 * tg + 1];
        }
    __syncthreads();

    const uint32_t aoff = (wm + (lane & 15)) * A_STRIDE + ((lane & 16) ? 16 : 0);
    const int rB  = (lane & 7) + ((lane & 16) ? 8 : 0);
    const uint32_t bko = (lane & 8) ? 16 : 0;

    // staging: 256 chunks of 16B per k16 tile (128 rows x 32B), 1 per thread
    const int srow = tid >> 1, sseg = tid & 1;

    for (int t = 0; t < NT; ++t) {
        const __half* __restrict__ hhp = g_hh[t & 1];

        auto src_of = [&](int kc) -> const uint4* {
            return (const uint4*)&hhp[srow * GH + g * NH + kc * 16 + sseg * 8];
        };
        auto dst_of = [&](int buf) -> uint4* {
            return (uint4*)(sm + A_BASE + buf * A_PLANE + srow * A_STRIDE + sseg * 16);
        };

        *dst_of(0) = __ldcg(src_of(0));
        __syncthreads();

        float acc[12][4] = {};

        for (int kc = 0; kc < 32; ++kc) {
            const int buf = kc & 1;
            uint4 nx;
            if (kc < 31) nx = __ldcg(src_of(kc + 1));

            uint32_t ah[4];
            ldsm4(ah, sb + A_BASE + buf * A_PLANE + aoff);

            const uint32_t kb = kc * 32 + bko;
            #pragma unroll
            for (int jp = 0; jp < 6; ++jp) {
                uint32_t bh4[4];
                ldsm4(bh4, sb + (jp * 16 + rB) * W_STRIDE + kb);
                mma_f16(acc[jp * 2],     ah, bh4);
                mma_f16(acc[jp * 2 + 1], ah, bh4 + 2);
            }

            if (kc < 31) *dst_of(buf ^ 1) = nx;
            __syncthreads();
        }

        // ---- Gate epilogue (acc[j]=reset, acc[j+4]=update, acc[j+8]=new) ----
        float* __restrict__ hout = g_h[(t + 1) & 1];
        const float* __restrict__ hin = g_h[t & 1];
        __half* __restrict__ nhh = g_hh[(t + 1) & 1];

        #pragma unroll
        for (int j = 0; j < 4; ++j)
            #pragma unroll
            for (int r = 0; r < 2; ++r) {
                const int row = wm + grp + r * 8;
                const int col = c0 + j * 8 + 2 * tg;
                const size_t hidx = (size_t)row * GH + g * NH + col;
                const size_t xb = (size_t)(row * NT + t) * NTOT + g * N3H;
                const float2 xr2 = *(const float2*)&g_xproj[xb + col];
                const float2 xz2 = *(const float2*)&g_xproj[xb + NH + col];
                const float2 xn2 = *(const float2*)&g_xproj[xb + 2 * NH + col];
                const float2 ho2 = __ldcg((const float2*)&hin[hidx]);
                float2 hn2;
                #pragma unroll
                for (int p = 0; p < 2; ++p) {
                    const float hr = acc[j    ][r * 2 + p] + bias[0][j][p];
                    const float hz = acc[j + 4][r * 2 + p] + bias[1][j][p];
                    const float hnv= acc[j + 8][r * 2 + p] + bias[2][j][p];
                    const float xr = p ? xr2.y : xr2.x;
                    const float xz = p ? xz2.y : xz2.x;
                    const float xn = p ? xn2.y : xn2.x;
                    const float ho = p ? ho2.y : ho2.x;
                    const float rr = 1.f / (1.f + __expf(-(xr + hr)));
                    const float uu = 1.f / (1.f + __expf(-(xz + hz)));
                    const float nn = tanhf(xn + rr * hnv);
                    const float hw = (1.f - uu) * nn + uu * ho;
                    if (p == 0) hn2.x = hw; else hn2.y = hw;
                }
                *(float2*)&hout[hidx] = hn2;
                __half2 h2;
                h2.x = __float2half_rn(hn2.x);
                h2.y = __float2half_rn(hn2.y);
                *(__half2*)&nhh[hidx] = h2;
                *(float2*)&out[(size_t)(row * NT + t) * GH + g * NH + col] = hn2;
            }

        // ---- group barrier: 16 CTAs of block g ----
        __threadfence();
        __syncthreads();
        if (tid == 0) {
            atomicAdd(&g_sync[g], 1);
            const int target = 16 * (t + 1);
            while (*(volatile int*)&g_sync[g] < target) { __nanosleep(64); }
        }
        __syncthreads();
    }
}

// ---------------------------------------------------------------------------
extern "C" void kernel_launch(void* const* d_in, const int* in_sizes, int n_in,
                              void* d_out, int out_size) {
    const float* z   = (const float*)d_in[0];
    const float* a   = (const float*)d_in[1];
    const float* h   = (const float*)d_in[2];
    const float* Wih = (const float*)d_in[3];
    const float* Whh = (const float*)d_in[4];
    const float* bih = (const float*)d_in[5];
    const float* bhh = (const float*)d_in[6];
    float* out = (float*)d_out;

    init_h<<<(NB * GH + 255) / 256, 256>>>(h);

    {
        size_t nx = (size_t)MTOT * KPC;
        pack_x_f16<<<(int)((nx + 255) / 256), 256>>>(z, a);
        size_t nw = (size_t)NTOT * KPC;
        pack_w_f16<<<(int)((nw + 255) / 256), 256>>>(Wih);
    }

    cudaFuncSetAttribute(xproj_f16, cudaFuncAttributeMaxDynamicSharedMemorySize, XS_SMEM);
    dim3 grid(NTOT / 128, MTOT / 128);   // (96, 64)
    xproj_f16<<<grid, 256, XS_SMEM>>>(bih);

    cudaFuncSetAttribute(gru_persistent, cudaFuncAttributeMaxDynamicSharedMemorySize, SMEM_GRU);
    gru_persistent<<<128, 256, SMEM_GRU>>>(Whh, bhh, out);
}

// round 10
// speedup vs baseline: 7.1729x; 1.1064x over previous
#include <cuda_runtime.h>
#include <cuda_fp16.h>
#include <stdint.h>
#include <math.h>

#define NG   8
#define NH   512
#define NI   1028
#define NB   128
#define NT   64
#define N3H  1536
#define NTOT (NG*N3H)    // 12288
#define MTOT (NB*NT)     // 8192
#define GH   (NG*NH)     // 4096

// fp16 xproj geometry
#define KPC  1056        // K padded to 33 * 32
#define KT32 33          // k-tiles of 32

// ---- global scratch (__device__: allocation-free rule) ----
__device__ __half g_Xp[(size_t)MTOT * KPC];
__device__ __half g_Wp[(size_t)NTOT * KPC];
__device__ float  g_xproj[(size_t)MTOT * NTOT];
__device__ float  g_h[2][NB * GH];          // fp32 h ping-pong (exact path)
__device__ __half g_hh[2][NB * GH];         // fp16 h planes for MMA
__device__ int    g_sync[NG];

// ---- helpers ----
__device__ __forceinline__ void mma_f16(float* c, const uint32_t* a, const uint32_t* b) {
    asm volatile(
        "mma.sync.aligned.m16n8k16.row.col.f32.f16.f16.f32 "
        "{%0,%1,%2,%3}, {%4,%5,%6,%7}, {%8,%9}, {%0,%1,%2,%3};"
        : "+f"(c[0]), "+f"(c[1]), "+f"(c[2]), "+f"(c[3])
        : "r"(a[0]), "r"(a[1]), "r"(a[2]), "r"(a[3]), "r"(b[0]), "r"(b[1]));
}
__device__ __forceinline__ void ldsm4(uint32_t* r, uint32_t addr) {
    asm volatile("ldmatrix.sync.aligned.m8n8.x4.shared.b16 {%0,%1,%2,%3}, [%4];"
                 : "=r"(r[0]), "=r"(r[1]), "=r"(r[2]), "=r"(r[3]) : "r"(addr));
}
__device__ __forceinline__ uint32_t smem_u32(const void* p) {
    uint32_t a;
    asm("{ .reg .u64 t; cvta.to.shared.u64 t, %1; cvt.u32.u64 %0, t; }" : "=r"(a) : "l"(p));
    return a;
}
__device__ __forceinline__ void cp16(uint32_t dst, const void* src) {
    asm volatile("cp.async.cg.shared.global [%0], [%1], 16;" :: "r"(dst), "l"(src));
}
#define CP_COMMIT()  asm volatile("cp.async.commit_group;" ::: "memory")
#define CP_WAIT(n)   asm volatile("cp.async.wait_group %0;" :: "n"(n) : "memory")

// ---------------------------------------------------------------------------
__global__ void init_h(const float* __restrict__ h0) {
    int i = blockIdx.x * blockDim.x + threadIdx.x;
    if (i < NB * GH) {
        float v = h0[i];
        g_h[0][i]  = v;
        g_hh[0][i] = __float2half_rn(v);
    }
    if (i < NG) g_sync[i] = 0;
}

// Pack X = concat(a,z) -> fp16 plane [MTOT][KPC]
__global__ void pack_x_f16(const float* __restrict__ z, const float* __restrict__ a) {
    size_t idx = (size_t)blockIdx.x * blockDim.x + threadIdx.x;
    if (idx >= (size_t)MTOT * KPC) return;
    int m = (int)(idx / KPC), k = (int)(idx % KPC);
    float v = 0.f;
    if (k < 4)       v = a[m * 4 + k];
    else if (k < NI) v = z[(size_t)m * 1024 + (k - 4)];
    g_Xp[idx] = __float2half_rn(v);
}

// Pack W_ih -> fp16 plane [NTOT][KPC]
__global__ void pack_w_f16(const float* __restrict__ Wih) {
    size_t idx = (size_t)blockIdx.x * blockDim.x + threadIdx.x;
    if (idx >= (size_t)NTOT * KPC) return;
    int n = (int)(idx / KPC), k = (int)(idx % KPC);
    g_Wp[idx] = __float2half_rn((k < NI) ? Wih[(size_t)n * NI + k] : 0.f);
}

// ---------------------------------------------------------------------------
// xproj = X @ W^T + b, fp16 single-term, fp32 accum. (unchanged from R9)
// ---------------------------------------------------------------------------
#define ROWB   80
#define PLANE  (128 * ROWB)      // 10240 B
#define STG    (2 * PLANE)
#define XS_SMEM (2 * STG)        // 40960 B

__global__ __launch_bounds__(256) void xproj_f16(const float* __restrict__ bih) {
    extern __shared__ char smem[];
    const uint32_t sb = smem_u32(smem);
    const int tid = threadIdx.x, lane = tid & 31, warp = tid >> 5;
    const int m0 = blockIdx.y * 128, n0 = blockIdx.x * 128;
    const int wm = (warp & 1) * 64, wn = (warp >> 1) * 32;
    const int grp = lane >> 2, tg = lane & 3;

    float c[4][4][4] = {};

    auto stage = [&](int kt, int b) {
        const uint32_t dst0 = sb + b * STG;
        #pragma unroll
        for (int u = 0; u < 4; ++u) {
            const int i = tid + u * 256;
            const int s = i >> 9;
            const int r = (i >> 2) & 127;
            const int ch = i & 3;
            const char* src = s
                ? (const char*)&g_Wp[(size_t)(n0 + r) * KPC]
                : (const char*)&g_Xp[(size_t)(m0 + r) * KPC];
            cp16(dst0 + s * PLANE + r * ROWB + ch * 16, src + kt * 64 + ch * 16);
        }
        CP_COMMIT();
    };

    stage(0, 0);

    const int rowA = wm + (lane & 15);
    const int kAoff = (lane & 16) ? 16 : 0;
    const int rowB = wn + (lane & 7) + ((lane & 16) ? 8 : 0);
    const int kBoff = (lane & 8) ? 16 : 0;

    for (int kt = 0; kt < KT32; ++kt) {
        const int b = kt & 1;
        if (kt + 1 < KT32) { stage(kt + 1, b ^ 1); CP_WAIT(1); }
        else               { CP_WAIT(0); }
        __syncthreads();

        const uint32_t base = sb + b * STG;
        #pragma unroll
        for (int ks = 0; ks < 2; ++ks) {
            uint32_t ah[4][4], bh[4][2];
            #pragma unroll
            for (int mi = 0; mi < 4; ++mi)
                ldsm4(ah[mi], base + (rowA + mi * 16) * ROWB + ks * 32 + kAoff);
            #pragma unroll
            for (int np = 0; np < 2; ++np) {
                uint32_t t4[4];
                ldsm4(t4, base + PLANE + (rowB + np * 16) * ROWB + ks * 32 + kBoff);
                bh[np * 2][0] = t4[0]; bh[np * 2][1] = t4[1];
                bh[np * 2 + 1][0] = t4[2]; bh[np * 2 + 1][1] = t4[3];
            }
            #pragma unroll
            for (int mi = 0; mi < 4; ++mi)
                #pragma unroll
                for (int nj = 0; nj < 4; ++nj)
                    mma_f16(c[mi][nj], ah[mi], bh[nj]);
        }
        __syncthreads();
    }

    #pragma unroll
    for (int nj = 0; nj < 4; ++nj) {
        const int col = n0 + wn + nj * 8 + 2 * tg;
        const float b0v = bih[col], b1v = bih[col + 1];
        #pragma unroll
        for (int mi = 0; mi < 4; ++mi) {
            const int r0 = m0 + wm + mi * 16 + grp;
            float2 v0 = make_float2(c[mi][nj][0] + b0v, c[mi][nj][1] + b1v);
            float2 v1 = make_float2(c[mi][nj][2] + b0v, c[mi][nj][3] + b1v);
            *(float2*)&g_xproj[(size_t)r0 * NTOT + col]       = v0;
            *(float2*)&g_xproj[(size_t)(r0 + 8) * NTOT + col] = v1;
        }
    }
}

// ---------------------------------------------------------------------------
// Persistent recurrence, sync-free mainloop.
// 128 CTAs = (g, 32-col chunk). Whh fp16 in smem once. A (h) fragments are
// loaded DIRECTLY from the global fp16 h plane per warp (__ldcg, L2-resident)
// with depth-2 prefetch — no staging, no __syncthreads in the k-loop.
// Gate-aligned accumulators; fp32 h for the exact u*h_old path.
// ---------------------------------------------------------------------------
#define W_STRIDE 1040
#define SMEM_GRU (96 * W_STRIDE)        // 99840

__global__ __launch_bounds__(256) void gru_persistent(
    const float* __restrict__ Whh, const float* __restrict__ bhh,
    float* __restrict__ out)
{
    extern __shared__ char sm[];
    const uint32_t sb = smem_u32(sm);

    const int tid  = threadIdx.x;
    const int g    = blockIdx.x >> 4;
    const int c0   = (blockIdx.x & 15) * 32;
    const int warp = tid >> 5, lane = tid & 31;
    const int grp  = lane >> 2, tg = lane & 3;
    const int wm   = warp * 16;

    // ---- Fill W plane once (rows n = gate*32 + cl, cols k) ----
    for (int idx = tid; idx < 96 * 512; idx += 256) {
        const int n = idx >> 9, k = idx & 511;
        const float v = Whh[(size_t)(g * N3H + (n >> 5) * NH + c0 + (n & 31)) * NH + k];
        *(__half*)(sm + n * W_STRIDE + k * 2) = __float2half_rn(v);
    }

    // ---- Loop-invariant biases ----
    float bias[3][4][2];
    #pragma unroll
    for (int gate = 0; gate < 3; ++gate)
        #pragma unroll
        for (int j = 0; j < 4; ++j) {
            bias[gate][j][0] = bhh[g * N3H + gate * NH + c0 + j * 8 + 2 * tg];
            bias[gate][j][1] = bhh[g * N3H + gate * NH + c0 + j * 8 + 2 * tg + 1];
        }
    __syncthreads();

    const int rB  = (lane & 7) + ((lane & 16) ? 8 : 0);
    const uint32_t bko = (lane & 8) ? 16 : 0;

    // Per-lane A-fragment base offsets (m16n8k16 A layout):
    //   a0: (wm+grp,   2tg)  a1: (wm+grp+8, 2tg)  a2/a3: +8 in k
    const size_t aRow0 = (size_t)(wm + grp) * GH + g * NH + 2 * tg;
    const size_t aRow1 = aRow0 + (size_t)8 * GH;

    for (int t = 0; t < NT; ++t) {
        const __half* __restrict__ hhp = g_hh[t & 1];

        auto lda = [&](uint32_t* f, int kc) {
            const int ko = kc * 16;
            f[0] = __ldcg((const uint32_t*)(hhp + aRow0 + ko));
            f[1] = __ldcg((const uint32_t*)(hhp + aRow1 + ko));
            f[2] = __ldcg((const uint32_t*)(hhp + aRow0 + ko + 8));
            f[3] = __ldcg((const uint32_t*)(hhp + aRow1 + ko + 8));
        };

        float acc[12][4] = {};
        uint32_t af[2][4];
        lda(af[0], 0);
        lda(af[1], 1);

        #pragma unroll 4
        for (int kc = 0; kc < 32; ++kc) {
            uint32_t ah[4];
            ah[0] = af[kc & 1][0]; ah[1] = af[kc & 1][1];
            ah[2] = af[kc & 1][2]; ah[3] = af[kc & 1][3];
            if (kc < 30) lda(af[kc & 1], kc + 2);

            const uint32_t kb = kc * 32 + bko;
            #pragma unroll
            for (int jp = 0; jp < 6; ++jp) {
                uint32_t bh4[4];
                ldsm4(bh4, sb + (jp * 16 + rB) * W_STRIDE + kb);
                mma_f16(acc[jp * 2],     ah, bh4);
                mma_f16(acc[jp * 2 + 1], ah, bh4 + 2);
            }
        }

        // ---- Gate epilogue (acc[j]=reset, acc[j+4]=update, acc[j+8]=new) ----
        float* __restrict__ hout = g_h[(t + 1) & 1];
        const float* __restrict__ hin = g_h[t & 1];
        __half* __restrict__ nhh = g_hh[(t + 1) & 1];

        #pragma unroll
        for (int j = 0; j < 4; ++j)
            #pragma unroll
            for (int r = 0; r < 2; ++r) {
                const int row = wm + grp + r * 8;
                const int col = c0 + j * 8 + 2 * tg;
                const size_t hidx = (size_t)row * GH + g * NH + col;
                const size_t xb = (size_t)(row * NT + t) * NTOT + g * N3H;
                const float2 xr2 = *(const float2*)&g_xproj[xb + col];
                const float2 xz2 = *(const float2*)&g_xproj[xb + NH + col];
                const float2 xn2 = *(const float2*)&g_xproj[xb + 2 * NH + col];
                const float2 ho2 = __ldcg((const float2*)&hin[hidx]);
                float2 hn2;
                #pragma unroll
                for (int p = 0; p < 2; ++p) {
                    const float hr = acc[j    ][r * 2 + p] + bias[0][j][p];
                    const float hz = acc[j + 4][r * 2 + p] + bias[1][j][p];
                    const float hnv= acc[j + 8][r * 2 + p] + bias[2][j][p];
                    const float xr = p ? xr2.y : xr2.x;
                    const float xz = p ? xz2.y : xz2.x;
                    const float xn = p ? xn2.y : xn2.x;
                    const float ho = p ? ho2.y : ho2.x;
                    const float rr = 1.f / (1.f + __expf(-(xr + hr)));
                    const float uu = 1.f / (1.f + __expf(-(xz + hz)));
                    const float nn = tanhf(xn + rr * hnv);
                    const float hw = (1.f - uu) * nn + uu * ho;
                    if (p == 0) hn2.x = hw; else hn2.y = hw;
                }
                *(float2*)&hout[hidx] = hn2;
                __half2 h2;
                h2.x = __float2half_rn(hn2.x);
                h2.y = __float2half_rn(hn2.y);
                *(__half2*)&nhh[hidx] = h2;
                *(float2*)&out[(size_t)(row * NT + t) * GH + g * NH + col] = hn2;
            }

        // ---- group barrier: 16 CTAs of block g ----
        __threadfence();
        __syncthreads();
        if (tid == 0) {
            atomicAdd(&g_sync[g], 1);
            const int target = 16 * (t + 1);
            while (*(volatile int*)&g_sync[g] < target) { __nanosleep(64); }
        }
        __syncthreads();
    }
}

// ---------------------------------------------------------------------------
extern "C" void kernel_launch(void* const* d_in, const int* in_sizes, int n_in,
                              void* d_out, int out_size) {
    const float* z   = (const float*)d_in[0];
    const float* a   = (const float*)d_in[1];
    const float* h   = (const float*)d_in[2];
    const float* Wih = (const float*)d_in[3];
    const float* Whh = (const float*)d_in[4];
    const float* bih = (const float*)d_in[5];
    const float* bhh = (const float*)d_in[6];
    float* out = (float*)d_out;

    init_h<<<(NB * GH + 255) / 256, 256>>>(h);

    {
        size_t nx = (size_t)MTOT * KPC;
        pack_x_f16<<<(int)((nx + 255) / 256), 256>>>(z, a);
        size_t nw = (size_t)NTOT * KPC;
        pack_w_f16<<<(int)((nw + 255) / 256), 256>>>(Wih);
    }

    cudaFuncSetAttribute(xproj_f16, cudaFuncAttributeMaxDynamicSharedMemorySize, XS_SMEM);
    dim3 grid(NTOT / 128, MTOT / 128);   // (96, 64)
    xproj_f16<<<grid, 256, XS_SMEM>>>(bih);

    cudaFuncSetAttribute(gru_persistent, cudaFuncAttributeMaxDynamicSharedMemorySize, SMEM_GRU);
    gru_persistent<<<128, 256, SMEM_GRU>>>(Whh, bhh, out);
}